// round 1
// baseline (speedup 1.0000x reference)
#include <cuda_runtime.h>
#include <math.h>

#define B_  4
#define S_  1024
#define D_  1024
#define H_  16
#define DH_ 64
#define DF_ 2048
#define M_  (B_*S_)

// ---------------- scratch (device globals; no allocation allowed) ----------
__device__ float g_h[M_ * D_];                 // LN output (reused for LN1 and LN2)
__device__ float g_qkv[(size_t)M_ * 3 * D_];   // QKV projection
__device__ float g_o[M_ * D_];                 // attention output
__device__ float g_x2[M_ * D_];                // x + attn out-proj (residual 1)
__device__ float g_ff[(size_t)M_ * DF_];       // FF1+GELU output

// ---------------- LayerNorm: one block per row, 256 threads, D=1024 --------
__global__ void ln_kernel(const float* __restrict__ x, const float* __restrict__ g,
                          const float* __restrict__ beta, float* __restrict__ y) {
    __shared__ float red[8];
    int row = blockIdx.x;
    int tid = threadIdx.x;
    const float4* xr = (const float4*)(x + (size_t)row * D_);
    float4 v = xr[tid];
    float s = v.x + v.y + v.z + v.w;
    #pragma unroll
    for (int o = 16; o; o >>= 1) s += __shfl_xor_sync(0xffffffffu, s, o);
    if ((tid & 31) == 0) red[tid >> 5] = s;
    __syncthreads();
    float tot = 0.f;
    #pragma unroll
    for (int i = 0; i < 8; i++) tot += red[i];
    float mu = tot * (1.0f / (float)D_);
    __syncthreads();
    float dx = v.x - mu, dy = v.y - mu, dz = v.z - mu, dw = v.w - mu;
    float sq = dx*dx + dy*dy + dz*dz + dw*dw;
    #pragma unroll
    for (int o = 16; o; o >>= 1) sq += __shfl_xor_sync(0xffffffffu, sq, o);
    if ((tid & 31) == 0) red[tid >> 5] = sq;
    __syncthreads();
    float tot2 = 0.f;
    #pragma unroll
    for (int i = 0; i < 8; i++) tot2 += red[i];
    float inv = rsqrtf(tot2 * (1.0f / (float)D_) + 1e-5f);
    float4 gg = ((const float4*)g)[tid];
    float4 bb = ((const float4*)beta)[tid];
    float4 o4;
    o4.x = dx * inv * gg.x + bb.x;
    o4.y = dy * inv * gg.y + bb.y;
    o4.z = dz * inv * gg.z + bb.z;
    o4.w = dw * inv * gg.w + bb.w;
    ((float4*)(y + (size_t)row * D_))[tid] = o4;
}

// ---------------- NT SGEMM: C[M,N] = A[M,K] @ B[N,K]^T + bias (+res)(+gelu) -
// 128x128 tile, BK=8, 256 threads, 8x8 microtile per thread.
__global__ __launch_bounds__(256, 2)
void gemm_nt_kernel(const float* __restrict__ A, const float* __restrict__ Bm,
                    const float* __restrict__ bias, const float* __restrict__ res,
                    float* __restrict__ C, int M, int N, int K, int act) {
    __shared__ float As[8][132];
    __shared__ float Bs[8][132];
    int tid = threadIdx.x;
    int bm = blockIdx.y << 7, bn = blockIdx.x << 7;
    int lrow = tid >> 1, lcol = (tid & 1) << 2;
    const float* Ag = A  + (size_t)(bm + lrow) * K + lcol;
    const float* Bg = Bm + (size_t)(bn + lrow) * K + lcol;
    int ty = tid >> 4, tx = tid & 15;
    float acc[8][8];
    #pragma unroll
    for (int i = 0; i < 8; i++)
        #pragma unroll
        for (int j = 0; j < 8; j++) acc[i][j] = 0.f;

    for (int k0 = 0; k0 < K; k0 += 8) {
        float4 a4 = *(const float4*)(Ag + k0);
        float4 b4 = *(const float4*)(Bg + k0);
        As[lcol + 0][lrow] = a4.x; As[lcol + 1][lrow] = a4.y;
        As[lcol + 2][lrow] = a4.z; As[lcol + 3][lrow] = a4.w;
        Bs[lcol + 0][lrow] = b4.x; Bs[lcol + 1][lrow] = b4.y;
        Bs[lcol + 2][lrow] = b4.z; Bs[lcol + 3][lrow] = b4.w;
        __syncthreads();
        #pragma unroll
        for (int k = 0; k < 8; k++) {
            float4 a0 = *(const float4*)&As[k][ty * 8];
            float4 a1 = *(const float4*)&As[k][ty * 8 + 4];
            float4 b0 = *(const float4*)&Bs[k][tx * 8];
            float4 b1 = *(const float4*)&Bs[k][tx * 8 + 4];
            float af[8] = {a0.x, a0.y, a0.z, a0.w, a1.x, a1.y, a1.z, a1.w};
            float bf[8] = {b0.x, b0.y, b0.z, b0.w, b1.x, b1.y, b1.z, b1.w};
            #pragma unroll
            for (int i = 0; i < 8; i++)
                #pragma unroll
                for (int j = 0; j < 8; j++)
                    acc[i][j] += af[i] * bf[j];
        }
        __syncthreads();
    }

    #pragma unroll
    for (int i = 0; i < 8; i++) {
        int row = bm + ty * 8 + i;
        float*       cr = C + (size_t)row * N + bn + tx * 8;
        const float* rr = res ? (res + (size_t)row * N + bn + tx * 8) : (const float*)0;
        float vout[8];
        #pragma unroll
        for (int j = 0; j < 8; j++) {
            float vv = acc[i][j] + bias[bn + tx * 8 + j];
            if (rr) vv += rr[j];
            if (act) vv = 0.5f * vv * (1.0f + erff(vv * 0.70710678118654752f));
            vout[j] = vv;
        }
        *(float4*)(cr)     = make_float4(vout[0], vout[1], vout[2], vout[3]);
        *(float4*)(cr + 4) = make_float4(vout[4], vout[5], vout[6], vout[7]);
    }
}

// ---------------- Fused causal attention with tanh softcap ------------------
// One block per (q-tile of 64, head, batch). 256 threads; thread (r, cg)
// owns query row r and a 16-wide slice (cg) of keys / output dims.
#define PAD 68
#define ATTN_SMEM (4 * 64 * PAD * (int)sizeof(float))

__global__ __launch_bounds__(256)
void attn_kernel(const float* __restrict__ qkv, float* __restrict__ o) {
    extern __shared__ float sm[];
    float* Qs  = sm;                  // [64][PAD]  Q rows
    float* Kst = sm + 64 * PAD;       // [64][PAD]  K transposed: Kst[d][j]
    float* Vs  = sm + 2 * 64 * PAD;   // [64][PAD]  V rows
    float* Ps  = sm + 3 * 64 * PAD;   // [64][PAD]  probabilities

    int qb = blockIdx.x, h = blockIdx.y, b = blockIdx.z;
    int tid = threadIdx.x;
    int r  = tid >> 2;      // query row within tile (0..63)
    int cg = tid & 3;       // 16-wide column group (0..3)
    const size_t rstride = 3 * D_;
    const float* base = qkv + (size_t)b * S_ * rstride + h * DH_;

    int lr = r, ld = cg * 16;
    // load Q tile
    {
        const float* qg = base + (size_t)(qb * 64 + lr) * rstride + ld;
        float* qs = Qs + lr * PAD + ld;
        #pragma unroll
        for (int i = 0; i < 16; i += 4) *(float4*)(qs + i) = *(const float4*)(qg + i);
    }

    float acc[16];
    #pragma unroll
    for (int i = 0; i < 16; i++) acc[i] = 0.f;
    float m_run = -INFINITY, l_run = 0.f;
    int qglob = qb * 64 + r;

    for (int kb = 0; kb <= qb; kb++) {
        __syncthreads();
        // load K (transposed into smem) and V
        {
            const float* kg = base + (size_t)(kb * 64 + lr) * rstride + D_ + ld;
            #pragma unroll
            for (int i = 0; i < 16; i += 4) {
                float4 kv = *(const float4*)(kg + i);
                Kst[(ld + i + 0) * PAD + lr] = kv.x;
                Kst[(ld + i + 1) * PAD + lr] = kv.y;
                Kst[(ld + i + 2) * PAD + lr] = kv.z;
                Kst[(ld + i + 3) * PAD + lr] = kv.w;
            }
            const float* vg = base + (size_t)(kb * 64 + lr) * rstride + 2 * D_ + ld;
            float* vs = Vs + lr * PAD + ld;
            #pragma unroll
            for (int i = 0; i < 16; i += 4) *(float4*)(vs + i) = *(const float4*)(vg + i);
        }
        __syncthreads();

        // S = Q K^T for this thread's 16 key columns
        float s[16];
        #pragma unroll
        for (int j = 0; j < 16; j++) s[j] = 0.f;
        const float* qrow = Qs + r * PAD;
        #pragma unroll 4
        for (int d = 0; d < 64; d++) {
            float qv = qrow[d];
            const float* kr = Kst + d * PAD + cg * 16;
            float4 k0 = *(const float4*)(kr);
            float4 k1 = *(const float4*)(kr + 4);
            float4 k2 = *(const float4*)(kr + 8);
            float4 k3 = *(const float4*)(kr + 12);
            s[0]  += qv * k0.x; s[1]  += qv * k0.y; s[2]  += qv * k0.z; s[3]  += qv * k0.w;
            s[4]  += qv * k1.x; s[5]  += qv * k1.y; s[6]  += qv * k1.z; s[7]  += qv * k1.w;
            s[8]  += qv * k2.x; s[9]  += qv * k2.y; s[10] += qv * k2.z; s[11] += qv * k2.w;
            s[12] += qv * k3.x; s[13] += qv * k3.y; s[14] += qv * k3.z; s[15] += qv * k3.w;
        }

        // scale, softcap, causal mask, online softmax
        float mt = -INFINITY;
        #pragma unroll
        for (int j = 0; j < 16; j++) {
            float sv = s[j] * 0.125f;                    // 1/sqrt(64)
            sv = 6.0f * tanhf(sv * (1.0f / 6.0f));       // logit softcap
            int kglob = kb * 64 + cg * 16 + j;
            if (kglob > qglob) sv = -INFINITY;           // causal
            s[j] = sv;
            mt = fmaxf(mt, sv);
        }
        mt = fmaxf(mt, __shfl_xor_sync(0xffffffffu, mt, 1));
        mt = fmaxf(mt, __shfl_xor_sync(0xffffffffu, mt, 2));
        float mnew  = fmaxf(m_run, mt);                  // finite: diag always unmasked
        float alpha = __expf(m_run - mnew);
        float psum  = 0.f;
        float* prow = Ps + r * PAD + cg * 16;
        #pragma unroll
        for (int j = 0; j < 16; j++) {
            float p = __expf(s[j] - mnew);
            prow[j] = p;
            psum += p;
        }
        psum += __shfl_xor_sync(0xffffffffu, psum, 1);
        psum += __shfl_xor_sync(0xffffffffu, psum, 2);
        l_run = l_run * alpha + psum;
        m_run = mnew;
        #pragma unroll
        for (int i = 0; i < 16; i++) acc[i] *= alpha;
        __syncthreads();

        // O += P V for this thread's 16 output dims
        const float* pr = Ps + r * PAD;
        #pragma unroll 4
        for (int j = 0; j < 64; j++) {
            float pv = pr[j];
            const float* vr = Vs + j * PAD + cg * 16;
            float4 v0 = *(const float4*)(vr);
            float4 v1 = *(const float4*)(vr + 4);
            float4 v2 = *(const float4*)(vr + 8);
            float4 v3 = *(const float4*)(vr + 12);
            acc[0]  += pv * v0.x; acc[1]  += pv * v0.y; acc[2]  += pv * v0.z; acc[3]  += pv * v0.w;
            acc[4]  += pv * v1.x; acc[5]  += pv * v1.y; acc[6]  += pv * v1.z; acc[7]  += pv * v1.w;
            acc[8]  += pv * v2.x; acc[9]  += pv * v2.y; acc[10] += pv * v2.z; acc[11] += pv * v2.w;
            acc[12] += pv * v3.x; acc[13] += pv * v3.y; acc[14] += pv * v3.z; acc[15] += pv * v3.w;
        }
    }

    float invl = 1.0f / l_run;
    float* orow = o + (size_t)(b * S_ + qglob) * D_ + h * DH_ + cg * 16;
    *(float4*)(orow)      = make_float4(acc[0]*invl,  acc[1]*invl,  acc[2]*invl,  acc[3]*invl);
    *(float4*)(orow + 4)  = make_float4(acc[4]*invl,  acc[5]*invl,  acc[6]*invl,  acc[7]*invl);
    *(float4*)(orow + 8)  = make_float4(acc[8]*invl,  acc[9]*invl,  acc[10]*invl, acc[11]*invl);
    *(float4*)(orow + 12) = make_float4(acc[12]*invl, acc[13]*invl, acc[14]*invl, acc[15]*invl);
}

// ---------------- launch ----------------------------------------------------
extern "C" void kernel_launch(void* const* d_in, const int* in_sizes, int n_in,
                              void* d_out, int out_size) {
    const float* x     = (const float*)d_in[0];
    // d_in[1] = mask (tril, hardcoded causal)
    const float* qkv_w = (const float*)d_in[2];
    const float* qkv_b = (const float*)d_in[3];
    const float* out_w = (const float*)d_in[4];
    const float* out_b = (const float*)d_in[5];
    const float* ln1_g = (const float*)d_in[6];
    const float* ln1_b = (const float*)d_in[7];
    const float* ln2_g = (const float*)d_in[8];
    const float* ln2_b = (const float*)d_in[9];
    const float* ff1_w = (const float*)d_in[10];
    const float* ff1_b = (const float*)d_in[11];
    const float* ff2_w = (const float*)d_in[12];
    const float* ff2_b = (const float*)d_in[13];
    float* out = (float*)d_out;

    float *h, *qkv, *o, *x2, *ff;
    cudaGetSymbolAddress((void**)&h,   g_h);
    cudaGetSymbolAddress((void**)&qkv, g_qkv);
    cudaGetSymbolAddress((void**)&o,   g_o);
    cudaGetSymbolAddress((void**)&x2,  g_x2);
    cudaGetSymbolAddress((void**)&ff,  g_ff);

    cudaFuncSetAttribute(attn_kernel, cudaFuncAttributeMaxDynamicSharedMemorySize, ATTN_SMEM);

    // 1. h = LN1(x)
    ln_kernel<<<M_, 256>>>(x, ln1_g, ln1_b, h);
    // 2. qkv = h @ qkv_w^T + qkv_b                         [4096, 3072]
    gemm_nt_kernel<<<dim3(3 * D_ / 128, M_ / 128), 256>>>(h, qkv_w, qkv_b, (const float*)0, qkv, M_, 3 * D_, D_, 0);
    // 3. o = causal softcap attention(qkv)                 [4096, 1024]
    attn_kernel<<<dim3(S_ / 64, H_, B_), 256, ATTN_SMEM>>>(qkv, o);
    // 4. x2 = x + o @ out_w^T + out_b                      [4096, 1024]
    gemm_nt_kernel<<<dim3(D_ / 128, M_ / 128), 256>>>(o, out_w, out_b, x, x2, M_, D_, D_, 0);
    // 5. h = LN2(x2)
    ln_kernel<<<M_, 256>>>(x2, ln2_g, ln2_b, h);
    // 6. ff = gelu(h @ ff1_w^T + ff1_b)                    [4096, 2048]
    gemm_nt_kernel<<<dim3(DF_ / 128, M_ / 128), 256>>>(h, ff1_w, ff1_b, (const float*)0, ff, M_, DF_, D_, 1);
    // 7. out = x2 + ff @ ff2_w^T + ff2_b                   [4096, 1024]
    gemm_nt_kernel<<<dim3(D_ / 128, M_ / 128), 256>>>(ff, ff2_w, ff2_b, x2, out, M_, D_, DF_, 0);
}

// round 3
// speedup vs baseline: 1.5527x; 1.5527x over previous
#include <cuda_runtime.h>
#include <math.h>
#include <stdint.h>

#define B_  4
#define S_  1024
#define D_  1024
#define H_  16
#define DH_ 64
#define DF_ 2048
#define M_  (B_*S_)

// ---------------- scratch (device globals; no allocation allowed) ----------
__device__ float g_h[M_ * D_];                 // LN output (tf32-rounded)
__device__ float g_qkv[(size_t)M_ * 3 * D_];   // QKV projection (full fp32)
__device__ float g_o[M_ * D_];                 // attention output (tf32-rounded)
__device__ float g_x2[M_ * D_];                // residual 1 (full fp32)
__device__ float g_ff[(size_t)M_ * DF_];       // FF1+GELU output (tf32-rounded)
__device__ float g_w[8 * 1024 * 1024];         // tf32-rounded weights

// ---------------- helpers ----------------------------------------------------
__device__ __forceinline__ uint32_t smem_u32(const void* p) {
    uint32_t a;
    asm("{ .reg .u64 t; cvta.to.shared.u64 t, %1; cvt.u32.u64 %0, t; }" : "=r"(a) : "l"(p));
    return a;
}
__device__ __forceinline__ float tf32r(float x) {
    uint32_t u; asm("cvt.rna.tf32.f32 %0, %1;" : "=r"(u) : "f"(x));
    return __uint_as_float(u);
}
__device__ __forceinline__ void cp16(uint32_t dst, const void* src) {
    asm volatile("cp.async.cg.shared.global [%0], [%1], 16;" :: "r"(dst), "l"(src) : "memory");
}
__device__ __forceinline__ void ldsm4(uint32_t* o, uint32_t addr) {
    asm volatile("ldmatrix.sync.aligned.m8n8.x4.shared.b16 {%0,%1,%2,%3}, [%4];"
                 : "=r"(o[0]), "=r"(o[1]), "=r"(o[2]), "=r"(o[3]) : "r"(addr));
}
__device__ __forceinline__ void mma_tf32(float* c, const uint32_t* a, uint32_t b0, uint32_t b1) {
    asm volatile(
        "mma.sync.aligned.m16n8k8.row.col.f32.tf32.tf32.f32 "
        "{%0,%1,%2,%3}, {%4,%5,%6,%7}, {%8,%9}, {%0,%1,%2,%3};"
        : "+f"(c[0]), "+f"(c[1]), "+f"(c[2]), "+f"(c[3])
        : "r"(a[0]), "r"(a[1]), "r"(a[2]), "r"(a[3]), "r"(b0), "r"(b1));
}

// ---------------- weight rounding (fp32 -> tf32-rounded fp32) ---------------
__global__ void round_tf32_kernel(const float4* __restrict__ s, float4* __restrict__ d, int n4) {
    int i = blockIdx.x * blockDim.x + threadIdx.x;
    if (i < n4) {
        float4 v = s[i];
        v.x = tf32r(v.x); v.y = tf32r(v.y); v.z = tf32r(v.z); v.w = tf32r(v.w);
        d[i] = v;
    }
}

// ---------------- LayerNorm (writes tf32-rounded output) --------------------
__global__ void ln_kernel(const float* __restrict__ x, const float* __restrict__ g,
                          const float* __restrict__ beta, float* __restrict__ y) {
    __shared__ float red[8];
    int row = blockIdx.x;
    int tid = threadIdx.x;
    const float4* xr = (const float4*)(x + (size_t)row * D_);
    float4 v = xr[tid];
    float s = v.x + v.y + v.z + v.w;
    #pragma unroll
    for (int o = 16; o; o >>= 1) s += __shfl_xor_sync(0xffffffffu, s, o);
    if ((tid & 31) == 0) red[tid >> 5] = s;
    __syncthreads();
    float tot = 0.f;
    #pragma unroll
    for (int i = 0; i < 8; i++) tot += red[i];
    float mu = tot * (1.0f / (float)D_);
    __syncthreads();
    float dx = v.x - mu, dy = v.y - mu, dz = v.z - mu, dw = v.w - mu;
    float sq = dx*dx + dy*dy + dz*dz + dw*dw;
    #pragma unroll
    for (int o = 16; o; o >>= 1) sq += __shfl_xor_sync(0xffffffffu, sq, o);
    if ((tid & 31) == 0) red[tid >> 5] = sq;
    __syncthreads();
    float tot2 = 0.f;
    #pragma unroll
    for (int i = 0; i < 8; i++) tot2 += red[i];
    float inv = rsqrtf(tot2 * (1.0f / (float)D_) + 1e-5f);
    float4 gg = ((const float4*)g)[tid];
    float4 bb = ((const float4*)beta)[tid];
    float4 o4;
    o4.x = tf32r(dx * inv * gg.x + bb.x);
    o4.y = tf32r(dy * inv * gg.y + bb.y);
    o4.z = tf32r(dz * inv * gg.z + bb.z);
    o4.w = tf32r(dw * inv * gg.w + bb.w);
    ((float4*)(y + (size_t)row * D_))[tid] = o4;
}

// ---------------- mma.sync tf32 GEMM: C[M,N] = A[M,K] @ B[N,K]^T + epilogue -
// CTA 128x128, BK=32, 8 warps (4x2), warp tile 32x64.
// smem stage: A[128][36] + B[128][36] floats (144B row stride), double buffer.
#define ASTRIDE_B   144                        // bytes per smem row (36 floats)
#define HALF_BYTES  18432                      // 128 * 144
#define STAGE_BYTES (2 * HALF_BYTES)           // A half + B half
#define G_SMEM      (2 * STAGE_BYTES)          // 73728

__global__ __launch_bounds__(256)
void gemm_mma_kernel(const float* __restrict__ A, const float* __restrict__ Bw,
                     const float* __restrict__ bias, const float* __restrict__ res,
                     float* __restrict__ C, int N, int K, int act, int round_out)
{
    extern __shared__ char smem[];
    uint32_t sb = smem_u32(smem);
    int tid = threadIdx.x;
    int lane = tid & 31, wid = tid >> 5;
    int wm = wid & 3, wn = wid >> 2;
    int bm = blockIdx.y << 7, bn = blockIdx.x << 7;

    // cp.async addressing: thread -> (row, half of 16 floats)
    int lrow = tid >> 1, lhalf = tid & 1;
    const float* ag = A  + (size_t)(bm + lrow) * K + lhalf * 16;
    const float* bg = Bw + (size_t)(bn + lrow) * K + lhalf * 16;
    uint32_t sda = sb + (uint32_t)lrow * ASTRIDE_B + (uint32_t)lhalf * 64;
    uint32_t sdb = sda + HALF_BYTES;

    // ldmatrix addressing
    int sel = lane >> 3, rr = lane & 7;
    uint32_t aaddr[2], baddr[4];
    #pragma unroll
    for (int mi = 0; mi < 2; mi++) {
        int row = wm * 32 + mi * 16 + (sel & 1) * 8 + rr;
        aaddr[mi] = sb + (uint32_t)row * ASTRIDE_B + (uint32_t)((sel >> 1) * 16);
    }
    #pragma unroll
    for (int ng = 0; ng < 4; ng++) {
        int row = wn * 64 + ng * 16 + (sel >> 1) * 8 + rr;
        baddr[ng] = sb + HALF_BYTES + (uint32_t)row * ASTRIDE_B + (uint32_t)((sel & 1) * 16);
    }

    float acc[2][8][4];
    #pragma unroll
    for (int mi = 0; mi < 2; mi++)
        #pragma unroll
        for (int ni = 0; ni < 8; ni++)
            #pragma unroll
            for (int j = 0; j < 4; j++) acc[mi][ni][j] = 0.f;

    int nk = K >> 5;

    // prologue: load stage 0
    {
        #pragma unroll
        for (int c = 0; c < 4; c++) { cp16(sda + c * 16, ag + c * 4); cp16(sdb + c * 16, bg + c * 4); }
        asm volatile("cp.async.commit_group;" ::: "memory");
    }

    for (int kt = 0; kt < nk; kt++) {
        if (kt + 1 < nk) {
            uint32_t so = (uint32_t)(((kt + 1) & 1) * STAGE_BYTES);
            const float* ag2 = ag + (kt + 1) * 32;
            const float* bg2 = bg + (kt + 1) * 32;
            #pragma unroll
            for (int c = 0; c < 4; c++) { cp16(sda + so + c * 16, ag2 + c * 4); cp16(sdb + so + c * 16, bg2 + c * 4); }
            asm volatile("cp.async.commit_group;" ::: "memory");
            asm volatile("cp.async.wait_group 1;" ::: "memory");
        } else {
            asm volatile("cp.async.wait_group 0;" ::: "memory");
        }
        __syncthreads();

        uint32_t so = (uint32_t)((kt & 1) * STAGE_BYTES);
        #pragma unroll
        for (int ks = 0; ks < 4; ks++) {
            uint32_t ko = so + (uint32_t)(ks * 32);
            uint32_t a[2][4];
            ldsm4(a[0], aaddr[0] + ko);
            ldsm4(a[1], aaddr[1] + ko);
            uint32_t b[4][4];
            #pragma unroll
            for (int ng = 0; ng < 4; ng++) ldsm4(b[ng], baddr[ng] + ko);
            #pragma unroll
            for (int mi = 0; mi < 2; mi++)
                #pragma unroll
                for (int ni = 0; ni < 8; ni++) {
                    int ng = ni >> 1, p = (ni & 1) * 2;
                    mma_tf32(acc[mi][ni], a[mi], b[ng][p], b[ng][p + 1]);
                }
        }
        __syncthreads();
    }

    // epilogue
    int gid = lane >> 2, tg = lane & 3;
    #pragma unroll
    for (int mi = 0; mi < 2; mi++) {
        #pragma unroll
        for (int half = 0; half < 2; half++) {
            int row = bm + wm * 32 + mi * 16 + half * 8 + gid;
            float* crow = C + (size_t)row * N;
            const float* rrow = res ? (res + (size_t)row * N) : (const float*)0;
            #pragma unroll
            for (int ni = 0; ni < 8; ni++) {
                int col = bn + wn * 64 + ni * 8 + tg * 2;
                float v0 = acc[mi][ni][half * 2 + 0] + __ldg(bias + col);
                float v1 = acc[mi][ni][half * 2 + 1] + __ldg(bias + col + 1);
                if (rrow) { v0 += rrow[col]; v1 += rrow[col + 1]; }
                if (act) {
                    v0 = 0.5f * v0 * (1.0f + erff(v0 * 0.70710678118654752f));
                    v1 = 0.5f * v1 * (1.0f + erff(v1 * 0.70710678118654752f));
                }
                if (round_out) { v0 = tf32r(v0); v1 = tf32r(v1); }
                *(float2*)(crow + col) = make_float2(v0, v1);
            }
        }
    }
}

// ---------------- Fused causal attention with tanh softcap ------------------
#define PAD 68
#define ATTN_SMEM (4 * 64 * PAD * (int)sizeof(float))

__global__ __launch_bounds__(256)
void attn_kernel(const float* __restrict__ qkv, float* __restrict__ o) {
    extern __shared__ float sm[];
    float* Qs  = sm;
    float* Kst = sm + 64 * PAD;
    float* Vs  = sm + 2 * 64 * PAD;
    float* Ps  = sm + 3 * 64 * PAD;

    int qb = blockIdx.x, h = blockIdx.y, b = blockIdx.z;
    int tid = threadIdx.x;
    int r  = tid >> 2;
    int cg = tid & 3;
    const size_t rstride = 3 * D_;
    const float* base = qkv + (size_t)b * S_ * rstride + h * DH_;

    int lr = r, ld = cg * 16;
    {
        const float* qg = base + (size_t)(qb * 64 + lr) * rstride + ld;
        float* qs = Qs + lr * PAD + ld;
        #pragma unroll
        for (int i = 0; i < 16; i += 4) *(float4*)(qs + i) = *(const float4*)(qg + i);
    }

    float acc[16];
    #pragma unroll
    for (int i = 0; i < 16; i++) acc[i] = 0.f;
    float m_run = -INFINITY, l_run = 0.f;
    int qglob = qb * 64 + r;

    for (int kb = 0; kb <= qb; kb++) {
        __syncthreads();
        {
            const float* kg = base + (size_t)(kb * 64 + lr) * rstride + D_ + ld;
            #pragma unroll
            for (int i = 0; i < 16; i += 4) {
                float4 kv = *(const float4*)(kg + i);
                Kst[(ld + i + 0) * PAD + lr] = kv.x;
                Kst[(ld + i + 1) * PAD + lr] = kv.y;
                Kst[(ld + i + 2) * PAD + lr] = kv.z;
                Kst[(ld + i + 3) * PAD + lr] = kv.w;
            }
            const float* vg = base + (size_t)(kb * 64 + lr) * rstride + 2 * D_ + ld;
            float* vs = Vs + lr * PAD + ld;
            #pragma unroll
            for (int i = 0; i < 16; i += 4) *(float4*)(vs + i) = *(const float4*)(vg + i);
        }
        __syncthreads();

        float s[16];
        #pragma unroll
        for (int j = 0; j < 16; j++) s[j] = 0.f;
        const float* qrow = Qs + r * PAD;
        #pragma unroll 4
        for (int d = 0; d < 64; d++) {
            float qv = qrow[d];
            const float* kr = Kst + d * PAD + cg * 16;
            float4 k0 = *(const float4*)(kr);
            float4 k1 = *(const float4*)(kr + 4);
            float4 k2 = *(const float4*)(kr + 8);
            float4 k3 = *(const float4*)(kr + 12);
            s[0]  += qv * k0.x; s[1]  += qv * k0.y; s[2]  += qv * k0.z; s[3]  += qv * k0.w;
            s[4]  += qv * k1.x; s[5]  += qv * k1.y; s[6]  += qv * k1.z; s[7]  += qv * k1.w;
            s[8]  += qv * k2.x; s[9]  += qv * k2.y; s[10] += qv * k2.z; s[11] += qv * k2.w;
            s[12] += qv * k3.x; s[13] += qv * k3.y; s[14] += qv * k3.z; s[15] += qv * k3.w;
        }

        float mt = -INFINITY;
        #pragma unroll
        for (int j = 0; j < 16; j++) {
            float sv = s[j] * 0.125f;
            sv = 6.0f * tanhf(sv * (1.0f / 6.0f));
            int kglob = kb * 64 + cg * 16 + j;
            if (kglob > qglob) sv = -INFINITY;
            s[j] = sv;
            mt = fmaxf(mt, sv);
        }
        mt = fmaxf(mt, __shfl_xor_sync(0xffffffffu, mt, 1));
        mt = fmaxf(mt, __shfl_xor_sync(0xffffffffu, mt, 2));
        float mnew  = fmaxf(m_run, mt);
        float alpha = __expf(m_run - mnew);
        float psum  = 0.f;
        float* prow = Ps + r * PAD + cg * 16;
        #pragma unroll
        for (int j = 0; j < 16; j++) {
            float p = __expf(s[j] - mnew);
            prow[j] = p;
            psum += p;
        }
        psum += __shfl_xor_sync(0xffffffffu, psum, 1);
        psum += __shfl_xor_sync(0xffffffffu, psum, 2);
        l_run = l_run * alpha + psum;
        m_run = mnew;
        #pragma unroll
        for (int i = 0; i < 16; i++) acc[i] *= alpha;
        __syncthreads();

        const float* pr = Ps + r * PAD;
        #pragma unroll 4
        for (int j = 0; j < 64; j++) {
            float pv = pr[j];
            const float* vr = Vs + j * PAD + cg * 16;
            float4 v0 = *(const float4*)(vr);
            float4 v1 = *(const float4*)(vr + 4);
            float4 v2 = *(const float4*)(vr + 8);
            float4 v3 = *(const float4*)(vr + 12);
            acc[0]  += pv * v0.x; acc[1]  += pv * v0.y; acc[2]  += pv * v0.z; acc[3]  += pv * v0.w;
            acc[4]  += pv * v1.x; acc[5]  += pv * v1.y; acc[6]  += pv * v1.z; acc[7]  += pv * v1.w;
            acc[8]  += pv * v2.x; acc[9]  += pv * v2.y; acc[10] += pv * v2.z; acc[11] += pv * v2.w;
            acc[12] += pv * v3.x; acc[13] += pv * v3.y; acc[14] += pv * v3.z; acc[15] += pv * v3.w;
        }
    }

    float invl = 1.0f / l_run;
    float* orow = o + (size_t)(b * S_ + qglob) * D_ + h * DH_ + cg * 16;
    #pragma unroll
    for (int i = 0; i < 16; i += 4)
        *(float4*)(orow + i) = make_float4(tf32r(acc[i]*invl),   tf32r(acc[i+1]*invl),
                                           tf32r(acc[i+2]*invl), tf32r(acc[i+3]*invl));
}

// ---------------- launch ----------------------------------------------------
extern "C" void kernel_launch(void* const* d_in, const int* in_sizes, int n_in,
                              void* d_out, int out_size) {
    const float* x     = (const float*)d_in[0];
    const float* qkv_w = (const float*)d_in[2];
    const float* qkv_b = (const float*)d_in[3];
    const float* out_w = (const float*)d_in[4];
    const float* out_b = (const float*)d_in[5];
    const float* ln1_g = (const float*)d_in[6];
    const float* ln1_b = (const float*)d_in[7];
    const float* ln2_g = (const float*)d_in[8];
    const float* ln2_b = (const float*)d_in[9];
    const float* ff1_w = (const float*)d_in[10];
    const float* ff1_b = (const float*)d_in[11];
    const float* ff2_w = (const float*)d_in[12];
    const float* ff2_b = (const float*)d_in[13];
    float* out = (float*)d_out;

    float *h, *qkv, *o, *x2, *ff, *w;
    cudaGetSymbolAddress((void**)&h,   g_h);
    cudaGetSymbolAddress((void**)&qkv, g_qkv);
    cudaGetSymbolAddress((void**)&o,   g_o);
    cudaGetSymbolAddress((void**)&x2,  g_x2);
    cudaGetSymbolAddress((void**)&ff,  g_ff);
    cudaGetSymbolAddress((void**)&w,   g_w);
    float* w_qkv = w;
    float* w_out = w + 3 * 1024 * 1024;
    float* w_ff1 = w + 4 * 1024 * 1024;
    float* w_ff2 = w + 6 * 1024 * 1024;

    cudaFuncSetAttribute(attn_kernel, cudaFuncAttributeMaxDynamicSharedMemorySize, ATTN_SMEM);
    cudaFuncSetAttribute(gemm_mma_kernel, cudaFuncAttributeMaxDynamicSharedMemorySize, G_SMEM);

    // 0. round weights to tf32 (rna)
    round_tf32_kernel<<<(3*1024*1024/4 + 255)/256, 256>>>((const float4*)qkv_w, (float4*)w_qkv, 3*1024*1024/4);
    round_tf32_kernel<<<(1024*1024/4   + 255)/256, 256>>>((const float4*)out_w, (float4*)w_out, 1024*1024/4);
    round_tf32_kernel<<<(2*1024*1024/4 + 255)/256, 256>>>((const float4*)ff1_w, (float4*)w_ff1, 2*1024*1024/4);
    round_tf32_kernel<<<(2*1024*1024/4 + 255)/256, 256>>>((const float4*)ff2_w, (float4*)w_ff2, 2*1024*1024/4);

    // 1. h = LN1(x)  (tf32-rounded)
    ln_kernel<<<M_, 256>>>(x, ln1_g, ln1_b, h);
    // 2. qkv = h @ qkv_w^T + qkv_b
    gemm_mma_kernel<<<dim3(3 * D_ / 128, M_ / 128), 256, G_SMEM>>>(h, w_qkv, qkv_b, (const float*)0, qkv, 3 * D_, D_, 0, 0);
    // 3. o = attention(qkv)  (tf32-rounded)
    attn_kernel<<<dim3(S_ / 64, H_, B_), 256, ATTN_SMEM>>>(qkv, o);
    // 4. x2 = x + o @ out_w^T + out_b
    gemm_mma_kernel<<<dim3(D_ / 128, M_ / 128), 256, G_SMEM>>>(o, w_out, out_b, x, x2, D_, D_, 0, 0);
    // 5. h = LN2(x2)  (tf32-rounded)
    ln_kernel<<<M_, 256>>>(x2, ln2_g, ln2_b, h);
    // 6. ff = gelu(h @ ff1_w^T + ff1_b)  (tf32-rounded)
    gemm_mma_kernel<<<dim3(DF_ / 128, M_ / 128), 256, G_SMEM>>>(h, w_ff1, ff1_b, (const float*)0, ff, DF_, D_, 1, 1);
    // 7. out = x2 + ff @ ff2_w^T + ff2_b
    gemm_mma_kernel<<<dim3(D_ / 128, M_ / 128), 256, G_SMEM>>>(ff, w_ff2, ff2_b, x2, out, D_, DF_, 0, 0);
}

// round 4
// speedup vs baseline: 3.4583x; 2.2272x over previous
#include <cuda_runtime.h>
#include <math.h>
#include <stdint.h>

#define B_  4
#define S_  1024
#define D_  1024
#define H_  16
#define DH_ 64
#define DF_ 2048
#define M_  (B_*S_)

// ---------------- scratch (device globals; no allocation allowed) ----------
__device__ float g_h[M_ * D_];
__device__ float g_qkv[(size_t)M_ * 3 * D_];
__device__ float g_o[M_ * D_];
__device__ float g_x2[M_ * D_];
__device__ float g_ff[(size_t)M_ * DF_];
__device__ float g_w[8 * 1024 * 1024];

// ---------------- helpers ----------------------------------------------------
__device__ __forceinline__ uint32_t smem_u32(const void* p) {
    uint32_t a;
    asm("{ .reg .u64 t; cvta.to.shared.u64 t, %1; cvt.u32.u64 %0, t; }" : "=r"(a) : "l"(p));
    return a;
}
__device__ __forceinline__ float tf32r(float x) {
    uint32_t u; asm("cvt.rna.tf32.f32 %0, %1;" : "=r"(u) : "f"(x));
    return __uint_as_float(u);
}
__device__ __forceinline__ void cp16(uint32_t dst, const void* src) {
    asm volatile("cp.async.cg.shared.global [%0], [%1], 16;" :: "r"(dst), "l"(src) : "memory");
}
__device__ __forceinline__ void ldsm4(uint32_t* o, uint32_t addr) {
    asm volatile("ldmatrix.sync.aligned.m8n8.x4.shared.b16 {%0,%1,%2,%3}, [%4];"
                 : "=r"(o[0]), "=r"(o[1]), "=r"(o[2]), "=r"(o[3]) : "r"(addr));
}
__device__ __forceinline__ void mma_tf32(float* c, const uint32_t* a, uint32_t b0, uint32_t b1) {
    asm volatile(
        "mma.sync.aligned.m16n8k8.row.col.f32.tf32.tf32.f32 "
        "{%0,%1,%2,%3}, {%4,%5,%6,%7}, {%8,%9}, {%0,%1,%2,%3};"
        : "+f"(c[0]), "+f"(c[1]), "+f"(c[2]), "+f"(c[3])
        : "r"(a[0]), "r"(a[1]), "r"(a[2]), "r"(a[3]), "r"(b0), "r"(b1));
}

// ---------------- weight rounding -------------------------------------------
__global__ void round_tf32_kernel(const float4* __restrict__ s, float4* __restrict__ d, int n4) {
    int i = blockIdx.x * blockDim.x + threadIdx.x;
    if (i < n4) {
        float4 v = s[i];
        v.x = tf32r(v.x); v.y = tf32r(v.y); v.z = tf32r(v.z); v.w = tf32r(v.w);
        d[i] = v;
    }
}

// ---------------- LayerNorm (tf32-rounded output) ---------------------------
__global__ void ln_kernel(const float* __restrict__ x, const float* __restrict__ g,
                          const float* __restrict__ beta, float* __restrict__ y) {
    __shared__ float red[8];
    int row = blockIdx.x;
    int tid = threadIdx.x;
    const float4* xr = (const float4*)(x + (size_t)row * D_);
    float4 v = xr[tid];
    float s = v.x + v.y + v.z + v.w;
    #pragma unroll
    for (int o = 16; o; o >>= 1) s += __shfl_xor_sync(0xffffffffu, s, o);
    if ((tid & 31) == 0) red[tid >> 5] = s;
    __syncthreads();
    float tot = 0.f;
    #pragma unroll
    for (int i = 0; i < 8; i++) tot += red[i];
    float mu = tot * (1.0f / (float)D_);
    __syncthreads();
    float dx = v.x - mu, dy = v.y - mu, dz = v.z - mu, dw = v.w - mu;
    float sq = dx*dx + dy*dy + dz*dz + dw*dw;
    #pragma unroll
    for (int o = 16; o; o >>= 1) sq += __shfl_xor_sync(0xffffffffu, sq, o);
    if ((tid & 31) == 0) red[tid >> 5] = sq;
    __syncthreads();
    float tot2 = 0.f;
    #pragma unroll
    for (int i = 0; i < 8; i++) tot2 += red[i];
    float inv = rsqrtf(tot2 * (1.0f / (float)D_) + 1e-5f);
    float4 gg = ((const float4*)g)[tid];
    float4 bb = ((const float4*)beta)[tid];
    float4 o4;
    o4.x = tf32r(dx * inv * gg.x + bb.x);
    o4.y = tf32r(dy * inv * gg.y + bb.y);
    o4.z = tf32r(dz * inv * gg.z + bb.z);
    o4.w = tf32r(dw * inv * gg.w + bb.w);
    ((float4*)(y + (size_t)row * D_))[tid] = o4;
}

// ---------------- mma.sync tf32 GEMM -----------------------------------------
#define ASTRIDE_B   144
#define HALF_BYTES  18432
#define STAGE_BYTES (2 * HALF_BYTES)
#define G_SMEM      (2 * STAGE_BYTES)

__global__ __launch_bounds__(256)
void gemm_mma_kernel(const float* __restrict__ A, const float* __restrict__ Bw,
                     const float* __restrict__ bias, const float* __restrict__ res,
                     float* __restrict__ C, int N, int K, int act, int round_out)
{
    extern __shared__ char smem[];
    uint32_t sb = smem_u32(smem);
    int tid = threadIdx.x;
    int lane = tid & 31, wid = tid >> 5;
    int wm = wid & 3, wn = wid >> 2;
    int bm = blockIdx.y << 7, bn = blockIdx.x << 7;

    int lrow = tid >> 1, lhalf = tid & 1;
    const float* ag = A  + (size_t)(bm + lrow) * K + lhalf * 16;
    const float* bg = Bw + (size_t)(bn + lrow) * K + lhalf * 16;
    uint32_t sda = sb + (uint32_t)lrow * ASTRIDE_B + (uint32_t)lhalf * 64;
    uint32_t sdb = sda + HALF_BYTES;

    int sel = lane >> 3, rr = lane & 7;
    uint32_t aaddr[2], baddr[4];
    #pragma unroll
    for (int mi = 0; mi < 2; mi++) {
        int row = wm * 32 + mi * 16 + (sel & 1) * 8 + rr;
        aaddr[mi] = sb + (uint32_t)row * ASTRIDE_B + (uint32_t)((sel >> 1) * 16);
    }
    #pragma unroll
    for (int ng = 0; ng < 4; ng++) {
        int row = wn * 64 + ng * 16 + (sel >> 1) * 8 + rr;
        baddr[ng] = sb + HALF_BYTES + (uint32_t)row * ASTRIDE_B + (uint32_t)((sel & 1) * 16);
    }

    float acc[2][8][4];
    #pragma unroll
    for (int mi = 0; mi < 2; mi++)
        #pragma unroll
        for (int ni = 0; ni < 8; ni++)
            #pragma unroll
            for (int j = 0; j < 4; j++) acc[mi][ni][j] = 0.f;

    int nk = K >> 5;
    {
        #pragma unroll
        for (int c = 0; c < 4; c++) { cp16(sda + c * 16, ag + c * 4); cp16(sdb + c * 16, bg + c * 4); }
        asm volatile("cp.async.commit_group;" ::: "memory");
    }

    for (int kt = 0; kt < nk; kt++) {
        if (kt + 1 < nk) {
            uint32_t so = (uint32_t)(((kt + 1) & 1) * STAGE_BYTES);
            const float* ag2 = ag + (kt + 1) * 32;
            const float* bg2 = bg + (kt + 1) * 32;
            #pragma unroll
            for (int c = 0; c < 4; c++) { cp16(sda + so + c * 16, ag2 + c * 4); cp16(sdb + so + c * 16, bg2 + c * 4); }
            asm volatile("cp.async.commit_group;" ::: "memory");
            asm volatile("cp.async.wait_group 1;" ::: "memory");
        } else {
            asm volatile("cp.async.wait_group 0;" ::: "memory");
        }
        __syncthreads();

        uint32_t so = (uint32_t)((kt & 1) * STAGE_BYTES);
        #pragma unroll
        for (int ks = 0; ks < 4; ks++) {
            uint32_t ko = so + (uint32_t)(ks * 32);
            uint32_t a[2][4];
            ldsm4(a[0], aaddr[0] + ko);
            ldsm4(a[1], aaddr[1] + ko);
            uint32_t b[4][4];
            #pragma unroll
            for (int ng = 0; ng < 4; ng++) ldsm4(b[ng], baddr[ng] + ko);
            #pragma unroll
            for (int mi = 0; mi < 2; mi++)
                #pragma unroll
                for (int ni = 0; ni < 8; ni++) {
                    int ng = ni >> 1, p = (ni & 1) * 2;
                    mma_tf32(acc[mi][ni], a[mi], b[ng][p], b[ng][p + 1]);
                }
        }
        __syncthreads();
    }

    int gid = lane >> 2, tg = lane & 3;
    #pragma unroll
    for (int mi = 0; mi < 2; mi++) {
        #pragma unroll
        for (int half = 0; half < 2; half++) {
            int row = bm + wm * 32 + mi * 16 + half * 8 + gid;
            float* crow = C + (size_t)row * N;
            const float* rrow = res ? (res + (size_t)row * N) : (const float*)0;
            #pragma unroll
            for (int ni = 0; ni < 8; ni++) {
                int col = bn + wn * 64 + ni * 8 + tg * 2;
                float v0 = acc[mi][ni][half * 2 + 0] + __ldg(bias + col);
                float v1 = acc[mi][ni][half * 2 + 1] + __ldg(bias + col + 1);
                if (rrow) { v0 += rrow[col]; v1 += rrow[col + 1]; }
                if (act) {
                    v0 = 0.5f * v0 * (1.0f + erff(v0 * 0.70710678118654752f));
                    v1 = 0.5f * v1 * (1.0f + erff(v1 * 0.70710678118654752f));
                }
                if (round_out) { v0 = tf32r(v0); v1 = tf32r(v1); }
                *(float2*)(crow + col) = make_float2(v0, v1);
            }
        }
    }
}

// ---------------- Tensor-core flash attention (tf32 mma) --------------------
// Block: (q-tile 64, head, batch), 128 threads = 4 warps, warp owns 16 q rows.
#define APAD 68
#define ATTN_SMEM (4 * 64 * APAD * (int)sizeof(float))

__global__ __launch_bounds__(128)
void attn_mma_kernel(const float* __restrict__ qkv, float* __restrict__ o_out) {
    extern __shared__ float sm[];
    float* Qs = sm;                   // [64][APAD] Q rows
    float* Ks = sm + 64 * APAD;       // [64][APAD] K rows [key][dh]
    float* Vt = sm + 2 * 64 * APAD;   // [64][APAD] V transposed [dh][key]
    float* Ps = sm + 3 * 64 * APAD;   // [64][APAD] probabilities

    int qb = blockIdx.x, h = blockIdx.y, b = blockIdx.z;
    int tid = threadIdx.x, lane = tid & 31, wid = tid >> 5;
    int gid = lane >> 2, tg = lane & 3;
    const size_t rstr = 3 * D_;
    const float* base = qkv + (size_t)b * S_ * rstr + h * DH_;

    int lr = tid >> 1, lh = tid & 1;  // loader: row, 32-float half
    // load Q tile once
    {
        const float* qg = base + (size_t)(qb * 64 + lr) * rstr + lh * 32;
        float* qs = Qs + lr * APAD + lh * 32;
        #pragma unroll
        for (int i = 0; i < 32; i += 4) *(float4*)(qs + i) = *(const float4*)(qg + i);
    }

    uint32_t sQ = smem_u32(Qs), sK = smem_u32(Ks), sV = smem_u32(Vt), sP = smem_u32(Ps);
    int sel = lane >> 3, rr = lane & 7;
    uint32_t qaddr = sQ + (uint32_t)(((wid * 16) + (sel & 1) * 8 + rr) * APAD * 4) + (uint32_t)((sel >> 1) * 16);
    uint32_t paddr = sP + (uint32_t)(((wid * 16) + (sel & 1) * 8 + rr) * APAD * 4) + (uint32_t)((sel >> 1) * 16);
    uint32_t kaddr[4], vaddr[4];
    #pragma unroll
    for (int ng = 0; ng < 4; ng++) {
        kaddr[ng] = sK + (uint32_t)((ng * 16 + (sel >> 1) * 8 + rr) * APAD * 4) + (uint32_t)((sel & 1) * 16);
        vaddr[ng] = sV + (uint32_t)((ng * 16 + (sel >> 1) * 8 + rr) * APAD * 4) + (uint32_t)((sel & 1) * 16);
    }

    float oa[8][4];
    #pragma unroll
    for (int ni = 0; ni < 8; ni++)
        #pragma unroll
        for (int j = 0; j < 4; j++) oa[ni][j] = 0.f;
    float m0 = -INFINITY, m1 = -INFINITY, l0 = 0.f, l1 = 0.f;
    int qr0 = qb * 64 + wid * 16 + gid;      // row0 global; row1 = qr0+8
    const float C1 = 0.125f / 6.0f;

    for (int kb = 0; kb <= qb; kb++) {
        __syncthreads();
        // load K rows; V transposed
        {
            const float* kg = base + (size_t)(kb * 64 + lr) * rstr + D_ + lh * 32;
            float* ks = Ks + lr * APAD + lh * 32;
            #pragma unroll
            for (int i = 0; i < 32; i += 4) *(float4*)(ks + i) = *(const float4*)(kg + i);
            const float* vg = base + (size_t)(kb * 64 + lr) * rstr + 2 * D_ + lh * 32;
            #pragma unroll
            for (int i = 0; i < 32; i += 4) {
                float4 v = *(const float4*)(vg + i);
                Vt[(lh * 32 + i + 0) * APAD + lr] = v.x;
                Vt[(lh * 32 + i + 1) * APAD + lr] = v.y;
                Vt[(lh * 32 + i + 2) * APAD + lr] = v.z;
                Vt[(lh * 32 + i + 3) * APAD + lr] = v.w;
            }
        }
        __syncthreads();

        // S = Q K^T (warp's 16 rows x 64 keys)
        float sc[8][4];
        #pragma unroll
        for (int ni = 0; ni < 8; ni++)
            #pragma unroll
            for (int j = 0; j < 4; j++) sc[ni][j] = 0.f;
        #pragma unroll
        for (int ks = 0; ks < 8; ks++) {
            uint32_t ko = (uint32_t)(ks * 32);
            uint32_t a[4];
            ldsm4(a, qaddr + ko);
            uint32_t bf[4][4];
            #pragma unroll
            for (int ng = 0; ng < 4; ng++) ldsm4(bf[ng], kaddr[ng] + ko);
            #pragma unroll
            for (int ni = 0; ni < 8; ni++) {
                int ng = ni >> 1, p = (ni & 1) * 2;
                mma_tf32(sc[ni], a, bf[ng][p], bf[ng][p + 1]);
            }
        }

        // softcap + causal mask + online softmax
        bool diag = (kb == qb);
        float mt0 = -INFINITY, mt1 = -INFINITY;
        #pragma unroll
        for (int ni = 0; ni < 8; ni++) {
            #pragma unroll
            for (int e = 0; e < 4; e++) {
                float y = sc[ni][e] * C1;
                float t = __expf(y + y);
                float v = 6.0f * (1.0f - __fdividef(2.0f, t + 1.0f));
                if (diag) {
                    int kcol = kb * 64 + ni * 8 + tg * 2 + (e & 1);
                    int qrow = qr0 + ((e >> 1) << 3);
                    if (kcol > qrow) v = -INFINITY;
                }
                sc[ni][e] = v;
                if (e < 2) mt0 = fmaxf(mt0, v); else mt1 = fmaxf(mt1, v);
            }
        }
        mt0 = fmaxf(mt0, __shfl_xor_sync(0xffffffffu, mt0, 1));
        mt0 = fmaxf(mt0, __shfl_xor_sync(0xffffffffu, mt0, 2));
        mt1 = fmaxf(mt1, __shfl_xor_sync(0xffffffffu, mt1, 1));
        mt1 = fmaxf(mt1, __shfl_xor_sync(0xffffffffu, mt1, 2));
        float mn0 = fmaxf(m0, mt0), mn1 = fmaxf(m1, mt1);
        float a0 = __expf(m0 - mn0), a1 = __expf(m1 - mn1);
        float s0 = 0.f, s1 = 0.f;
        float* p0 = Ps + (wid * 16 + gid) * APAD + tg * 2;
        float* p1 = p0 + 8 * APAD;
        #pragma unroll
        for (int ni = 0; ni < 8; ni++) {
            float e00 = __expf(sc[ni][0] - mn0);
            float e01 = __expf(sc[ni][1] - mn0);
            float e10 = __expf(sc[ni][2] - mn1);
            float e11 = __expf(sc[ni][3] - mn1);
            s0 += e00 + e01; s1 += e10 + e11;
            *(float2*)(p0 + ni * 8) = make_float2(tf32r(e00), tf32r(e01));
            *(float2*)(p1 + ni * 8) = make_float2(tf32r(e10), tf32r(e11));
        }
        s0 += __shfl_xor_sync(0xffffffffu, s0, 1);
        s0 += __shfl_xor_sync(0xffffffffu, s0, 2);
        s1 += __shfl_xor_sync(0xffffffffu, s1, 1);
        s1 += __shfl_xor_sync(0xffffffffu, s1, 2);
        l0 = l0 * a0 + s0; l1 = l1 * a1 + s1;
        m0 = mn0; m1 = mn1;
        #pragma unroll
        for (int ni = 0; ni < 8; ni++) {
            oa[ni][0] *= a0; oa[ni][1] *= a0;
            oa[ni][2] *= a1; oa[ni][3] *= a1;
        }
        __syncwarp();

        // O += P @ V  (A = P from smem, B = Vt [dh][key])
        #pragma unroll
        for (int ks = 0; ks < 8; ks++) {
            uint32_t ko = (uint32_t)(ks * 32);
            uint32_t a[4];
            ldsm4(a, paddr + ko);
            uint32_t bf[4][4];
            #pragma unroll
            for (int ng = 0; ng < 4; ng++) ldsm4(bf[ng], vaddr[ng] + ko);
            #pragma unroll
            for (int ni = 0; ni < 8; ni++) {
                int ng = ni >> 1, p = (ni & 1) * 2;
                mma_tf32(oa[ni], a, bf[ng][p], bf[ng][p + 1]);
            }
        }
    }

    float inv0 = 1.0f / l0, inv1 = 1.0f / l1;
    float* orow0 = o_out + (size_t)(b * S_ + qr0) * D_ + h * DH_ + tg * 2;
    float* orow1 = orow0 + 8 * (size_t)D_;
    #pragma unroll
    for (int ni = 0; ni < 8; ni++) {
        *(float2*)(orow0 + ni * 8) = make_float2(tf32r(oa[ni][0] * inv0), tf32r(oa[ni][1] * inv0));
        *(float2*)(orow1 + ni * 8) = make_float2(tf32r(oa[ni][2] * inv1), tf32r(oa[ni][3] * inv1));
    }
}

// ---------------- launch ------------------------------------------------------
extern "C" void kernel_launch(void* const* d_in, const int* in_sizes, int n_in,
                              void* d_out, int out_size) {
    const float* x     = (const float*)d_in[0];
    const float* qkv_w = (const float*)d_in[2];
    const float* qkv_b = (const float*)d_in[3];
    const float* out_w = (const float*)d_in[4];
    const float* out_b = (const float*)d_in[5];
    const float* ln1_g = (const float*)d_in[6];
    const float* ln1_b = (const float*)d_in[7];
    const float* ln2_g = (const float*)d_in[8];
    const float* ln2_b = (const float*)d_in[9];
    const float* ff1_w = (const float*)d_in[10];
    const float* ff1_b = (const float*)d_in[11];
    const float* ff2_w = (const float*)d_in[12];
    const float* ff2_b = (const float*)d_in[13];
    float* out = (float*)d_out;

    float *h, *qkv, *o, *x2, *ff, *w;
    cudaGetSymbolAddress((void**)&h,   g_h);
    cudaGetSymbolAddress((void**)&qkv, g_qkv);
    cudaGetSymbolAddress((void**)&o,   g_o);
    cudaGetSymbolAddress((void**)&x2,  g_x2);
    cudaGetSymbolAddress((void**)&ff,  g_ff);
    cudaGetSymbolAddress((void**)&w,   g_w);
    float* w_qkv = w;
    float* w_out = w + 3 * 1024 * 1024;
    float* w_ff1 = w + 4 * 1024 * 1024;
    float* w_ff2 = w + 6 * 1024 * 1024;

    cudaFuncSetAttribute(attn_mma_kernel, cudaFuncAttributeMaxDynamicSharedMemorySize, ATTN_SMEM);
    cudaFuncSetAttribute(gemm_mma_kernel, cudaFuncAttributeMaxDynamicSharedMemorySize, G_SMEM);

    round_tf32_kernel<<<(3*1024*1024/4 + 255)/256, 256>>>((const float4*)qkv_w, (float4*)w_qkv, 3*1024*1024/4);
    round_tf32_kernel<<<(1024*1024/4   + 255)/256, 256>>>((const float4*)out_w, (float4*)w_out, 1024*1024/4);
    round_tf32_kernel<<<(2*1024*1024/4 + 255)/256, 256>>>((const float4*)ff1_w, (float4*)w_ff1, 2*1024*1024/4);
    round_tf32_kernel<<<(2*1024*1024/4 + 255)/256, 256>>>((const float4*)ff2_w, (float4*)w_ff2, 2*1024*1024/4);

    // 1. h = LN1(x)
    ln_kernel<<<M_, 256>>>(x, ln1_g, ln1_b, h);
    // 2. qkv = h @ qkv_w^T + qkv_b  (tf32-rounded output for attention mma)
    gemm_mma_kernel<<<dim3(3 * D_ / 128, M_ / 128), 256, G_SMEM>>>(h, w_qkv, qkv_b, (const float*)0, qkv, 3 * D_, D_, 0, 1);
    // 3. o = tensor-core flash attention
    attn_mma_kernel<<<dim3(S_ / 64, H_, B_), 128, ATTN_SMEM>>>(qkv, o);
    // 4. x2 = x + o @ out_w^T + out_b
    gemm_mma_kernel<<<dim3(D_ / 128, M_ / 128), 256, G_SMEM>>>(o, w_out, out_b, x, x2, D_, D_, 0, 0);
    // 5. h = LN2(x2)
    ln_kernel<<<M_, 256>>>(x2, ln2_g, ln2_b, h);
    // 6. ff = gelu(h @ ff1_w^T + ff1_b)
    gemm_mma_kernel<<<dim3(DF_ / 128, M_ / 128), 256, G_SMEM>>>(h, w_ff1, ff1_b, (const float*)0, ff, DF_, D_, 1, 1);
    // 7. out = x2 + ff @ ff2_w^T + ff2_b
    gemm_mma_kernel<<<dim3(D_ / 128, M_ / 128), 256, G_SMEM>>>(ff, w_ff2, ff2_b, x2, out, D_, DF_, 0, 0);
}

// round 5
// speedup vs baseline: 7.1361x; 2.0635x over previous
#include <cuda_runtime.h>
#include <cuda_fp16.h>
#include <math.h>
#include <stdint.h>

#define B_  4
#define S_  1024
#define D_  1024
#define H_  16
#define DH_ 64
#define DF_ 2048
#define M_  (B_*S_)

// ---------------- scratch (device globals) ----------------------------------
__device__ __half g_h_h[M_ * D_];                 // LN output (fp16)
__device__ __half g_qkv_h[(size_t)M_ * 3 * D_];   // QKV (fp16)
__device__ __half g_o_h[M_ * D_];                 // attention out (fp16)
__device__ __half g_ff_h[(size_t)M_ * DF_];       // FF1+GELU (fp16)
__device__ float  g_x2[M_ * D_];                  // residual 1 (fp32)
__device__ __half g_wh[8 * 1024 * 1024];          // fp16 weights:
                                                  // [0,3M) qkv, [3M,4M) out,
                                                  // [4M,6M) ff1, [6M,8M) ff2

// ---------------- helpers ----------------------------------------------------
__device__ __forceinline__ uint32_t smem_u32(const void* p) {
    uint32_t a;
    asm("{ .reg .u64 t; cvta.to.shared.u64 t, %1; cvt.u32.u64 %0, t; }" : "=r"(a) : "l"(p));
    return a;
}
__device__ __forceinline__ void cp16(uint32_t dst, const void* src) {
    asm volatile("cp.async.cg.shared.global [%0], [%1], 16;" :: "r"(dst), "l"(src) : "memory");
}
__device__ __forceinline__ void ldsm4(uint32_t* o, uint32_t addr) {
    asm volatile("ldmatrix.sync.aligned.m8n8.x4.shared.b16 {%0,%1,%2,%3}, [%4];"
                 : "=r"(o[0]), "=r"(o[1]), "=r"(o[2]), "=r"(o[3]) : "r"(addr));
}
__device__ __forceinline__ void ldsm4t(uint32_t* o, uint32_t addr) {
    asm volatile("ldmatrix.sync.aligned.m8n8.x4.trans.shared.b16 {%0,%1,%2,%3}, [%4];"
                 : "=r"(o[0]), "=r"(o[1]), "=r"(o[2]), "=r"(o[3]) : "r"(addr));
}
__device__ __forceinline__ void mma_f16(float* c, const uint32_t* a, uint32_t b0, uint32_t b1) {
    asm volatile(
        "mma.sync.aligned.m16n8k16.row.col.f32.f16.f16.f32 "
        "{%0,%1,%2,%3}, {%4,%5,%6,%7}, {%8,%9}, {%0,%1,%2,%3};"
        : "+f"(c[0]), "+f"(c[1]), "+f"(c[2]), "+f"(c[3])
        : "r"(a[0]), "r"(a[1]), "r"(a[2]), "r"(a[3]), "r"(b0), "r"(b1));
}

// ---------------- weight conversion fp32 -> fp16 -----------------------------
__global__ void w2h_kernel(const float2* __restrict__ s, __half2* __restrict__ d, int n2) {
    int i = blockIdx.x * blockDim.x + threadIdx.x;
    if (i < n2) d[i] = __float22half2_rn(s[i]);
}

// ---------------- LayerNorm (fp32 in, fp16 out) ------------------------------
__global__ void ln_kernel(const float* __restrict__ x, const float* __restrict__ g,
                          const float* __restrict__ beta, __half* __restrict__ y) {
    __shared__ float red[8];
    int row = blockIdx.x;
    int tid = threadIdx.x;
    const float4* xr = (const float4*)(x + (size_t)row * D_);
    float4 v = xr[tid];
    float s = v.x + v.y + v.z + v.w;
    #pragma unroll
    for (int o = 16; o; o >>= 1) s += __shfl_xor_sync(0xffffffffu, s, o);
    if ((tid & 31) == 0) red[tid >> 5] = s;
    __syncthreads();
    float tot = 0.f;
    #pragma unroll
    for (int i = 0; i < 8; i++) tot += red[i];
    float mu = tot * (1.0f / (float)D_);
    __syncthreads();
    float dx = v.x - mu, dy = v.y - mu, dz = v.z - mu, dw = v.w - mu;
    float sq = dx*dx + dy*dy + dz*dz + dw*dw;
    #pragma unroll
    for (int o = 16; o; o >>= 1) sq += __shfl_xor_sync(0xffffffffu, sq, o);
    if ((tid & 31) == 0) red[tid >> 5] = sq;
    __syncthreads();
    float tot2 = 0.f;
    #pragma unroll
    for (int i = 0; i < 8; i++) tot2 += red[i];
    float inv = rsqrtf(tot2 * (1.0f / (float)D_) + 1e-5f);
    float4 gg = ((const float4*)g)[tid];
    float4 bb = ((const float4*)beta)[tid];
    __half2* yr = (__half2*)(y + (size_t)row * D_);
    yr[tid * 2]     = __floats2half2_rn(dx * inv * gg.x + bb.x, dy * inv * gg.y + bb.y);
    yr[tid * 2 + 1] = __floats2half2_rn(dz * inv * gg.z + bb.z, dw * inv * gg.w + bb.w);
}

// ---------------- fp16 mma GEMM: C[M,N] = A[M,K] @ B[N,K]^T + epilogue -------
// CTA 128x128, BK=32 halves, 8 warps (4x2), warp tile 32x64.
// smem row: 32 halves (64B) + 16B pad = 80B stride; double buffered.
#define GH_STRIDE 80
#define GH_HALF   (128 * GH_STRIDE)     // 10240
#define GH_STAGE  (2 * GH_HALF)         // 20480
#define GH_SMEM   (2 * GH_STAGE)        // 40960

__global__ __launch_bounds__(256)
void gemm_h_kernel(const __half* __restrict__ A, const __half* __restrict__ Bw,
                   const float* __restrict__ bias, const float* __restrict__ res,
                   float* __restrict__ C, __half* __restrict__ Ch,
                   int N, int K, int act)
{
    extern __shared__ char smem[];
    uint32_t sb = smem_u32(smem);
    int tid = threadIdx.x;
    int lane = tid & 31, wid = tid >> 5;
    int wm = wid & 3, wn = wid >> 2;
    int bm = blockIdx.y << 7, bn = blockIdx.x << 7;

    int lrow = tid >> 1, lhalf = tid & 1;
    const __half* ag = A  + (size_t)(bm + lrow) * K + lhalf * 16;
    const __half* bg = Bw + (size_t)(bn + lrow) * K + lhalf * 16;
    uint32_t sda = sb + (uint32_t)lrow * GH_STRIDE + (uint32_t)lhalf * 32;
    uint32_t sdb = sda + GH_HALF;

    int sel = lane >> 3, rr = lane & 7;
    uint32_t aaddr[2], baddr[4];
    #pragma unroll
    for (int mi = 0; mi < 2; mi++) {
        int row = wm * 32 + mi * 16 + (sel & 1) * 8 + rr;
        aaddr[mi] = sb + (uint32_t)row * GH_STRIDE + (uint32_t)((sel >> 1) * 16);
    }
    #pragma unroll
    for (int ng = 0; ng < 4; ng++) {
        int row = wn * 64 + ng * 16 + (sel >> 1) * 8 + rr;
        baddr[ng] = sb + GH_HALF + (uint32_t)row * GH_STRIDE + (uint32_t)((sel & 1) * 16);
    }

    float acc[2][8][4];
    #pragma unroll
    for (int mi = 0; mi < 2; mi++)
        #pragma unroll
        for (int ni = 0; ni < 8; ni++)
            #pragma unroll
            for (int j = 0; j < 4; j++) acc[mi][ni][j] = 0.f;

    int nk = K >> 5;
    {
        #pragma unroll
        for (int c = 0; c < 2; c++) { cp16(sda + c * 16, ag + c * 8); cp16(sdb + c * 16, bg + c * 8); }
        asm volatile("cp.async.commit_group;" ::: "memory");
    }

    for (int kt = 0; kt < nk; kt++) {
        if (kt + 1 < nk) {
            uint32_t so = (uint32_t)(((kt + 1) & 1) * GH_STAGE);
            const __half* ag2 = ag + (size_t)(kt + 1) * 32;
            const __half* bg2 = bg + (size_t)(kt + 1) * 32;
            #pragma unroll
            for (int c = 0; c < 2; c++) { cp16(sda + so + c * 16, ag2 + c * 8); cp16(sdb + so + c * 16, bg2 + c * 8); }
            asm volatile("cp.async.commit_group;" ::: "memory");
            asm volatile("cp.async.wait_group 1;" ::: "memory");
        } else {
            asm volatile("cp.async.wait_group 0;" ::: "memory");
        }
        __syncthreads();

        uint32_t so = (uint32_t)((kt & 1) * GH_STAGE);
        #pragma unroll
        for (int ks = 0; ks < 2; ks++) {
            uint32_t ko = so + (uint32_t)(ks * 32);
            uint32_t a[2][4];
            ldsm4(a[0], aaddr[0] + ko);
            ldsm4(a[1], aaddr[1] + ko);
            uint32_t b[4][4];
            #pragma unroll
            for (int ng = 0; ng < 4; ng++) ldsm4(b[ng], baddr[ng] + ko);
            #pragma unroll
            for (int mi = 0; mi < 2; mi++)
                #pragma unroll
                for (int ni = 0; ni < 8; ni++) {
                    int ng = ni >> 1, j = ni & 1;
                    mma_f16(acc[mi][ni], a[mi], b[ng][2 * j], b[ng][2 * j + 1]);
                }
        }
        __syncthreads();
    }

    int gid = lane >> 2, tg = lane & 3;
    #pragma unroll
    for (int mi = 0; mi < 2; mi++) {
        #pragma unroll
        for (int half = 0; half < 2; half++) {
            int row = bm + wm * 32 + mi * 16 + half * 8 + gid;
            const float* rrow = res ? (res + (size_t)row * N) : (const float*)0;
            #pragma unroll
            for (int ni = 0; ni < 8; ni++) {
                int col = bn + wn * 64 + ni * 8 + tg * 2;
                float v0 = acc[mi][ni][half * 2 + 0] + __ldg(bias + col);
                float v1 = acc[mi][ni][half * 2 + 1] + __ldg(bias + col + 1);
                if (rrow) { v0 += rrow[col]; v1 += rrow[col + 1]; }
                if (act) {
                    v0 = 0.5f * v0 * (1.0f + erff(v0 * 0.70710678118654752f));
                    v1 = 0.5f * v1 * (1.0f + erff(v1 * 0.70710678118654752f));
                }
                if (Ch) {
                    *(__half2*)(Ch + (size_t)row * N + col) = __floats2half2_rn(v0, v1);
                } else {
                    *(float2*)(C + (size_t)row * N + col) = make_float2(v0, v1);
                }
            }
        }
    }
}

// ---------------- fp16 tensor-core flash attention ---------------------------
// Block: (q-tile 64, head, batch), 128 threads = 4 warps, warp owns 16 q rows.
#define AST 72                                  // halves per smem row (144B)
__global__ __launch_bounds__(128)
void attn_h_kernel(const __half* __restrict__ qkv, __half* __restrict__ o_out) {
    __shared__ __half Qs[64 * AST];
    __shared__ __half Ks[64 * AST];
    __shared__ __half Vs[64 * AST];   // natural [key][dh]
    __shared__ __half Ps[64 * AST];

    int qb = blockIdx.x, h = blockIdx.y, b = blockIdx.z;
    int tid = threadIdx.x, lane = tid & 31, wid = tid >> 5;
    int gid = lane >> 2, tg = lane & 3;
    const size_t rstr = 3 * D_;
    const __half* base = qkv + (size_t)b * S_ * rstr + h * DH_;

    int lr = tid >> 1, lh = tid & 1;   // loader: row 0..63, 32-half half
    {
        const __half* qg = base + (size_t)(qb * 64 + lr) * rstr + lh * 32;
        __half* qs = Qs + lr * AST + lh * 32;
        #pragma unroll
        for (int i = 0; i < 32; i += 8) *(uint4*)(qs + i) = *(const uint4*)(qg + i);
    }

    uint32_t sQ = smem_u32(Qs), sK = smem_u32(Ks), sV = smem_u32(Vs), sP = smem_u32(Ps);
    int sel = lane >> 3, rr = lane & 7;
    uint32_t qaddr = sQ + (uint32_t)((wid * 16 + (sel & 1) * 8 + rr) * AST * 2) + (uint32_t)((sel >> 1) * 16);
    uint32_t paddr = sP + (uint32_t)((wid * 16 + (sel & 1) * 8 + rr) * AST * 2) + (uint32_t)((sel >> 1) * 16);
    uint32_t kaddr[4], vaddr[4];
    #pragma unroll
    for (int ng = 0; ng < 4; ng++) {
        kaddr[ng] = sK + (uint32_t)((ng * 16 + (sel >> 1) * 8 + rr) * AST * 2) + (uint32_t)((sel & 1) * 16);
        // trans ldmatrix for V: rows = key, 16B = 8 dh-halves
        vaddr[ng] = sV + (uint32_t)(((sel & 1) * 8 + rr) * AST * 2) + (uint32_t)(ng * 32 + (sel >> 1) * 16);
    }

    float oa[8][4];
    #pragma unroll
    for (int ni = 0; ni < 8; ni++)
        #pragma unroll
        for (int j = 0; j < 4; j++) oa[ni][j] = 0.f;
    float m0 = -INFINITY, m1 = -INFINITY, l0 = 0.f, l1 = 0.f;
    int qr0 = qb * 64 + wid * 16 + gid;
    const float C1 = 0.125f / 6.0f;

    for (int kb = 0; kb <= qb; kb++) {
        __syncthreads();
        {
            const __half* kg = base + (size_t)(kb * 64 + lr) * rstr + D_ + lh * 32;
            __half* ks = Ks + lr * AST + lh * 32;
            #pragma unroll
            for (int i = 0; i < 32; i += 8) *(uint4*)(ks + i) = *(const uint4*)(kg + i);
            const __half* vg = base + (size_t)(kb * 64 + lr) * rstr + 2 * D_ + lh * 32;
            __half* vs = Vs + lr * AST + lh * 32;
            #pragma unroll
            for (int i = 0; i < 32; i += 8) *(uint4*)(vs + i) = *(const uint4*)(vg + i);
        }
        __syncthreads();

        // S = Q K^T : 16 q rows x 64 keys, dh=64 -> 4 k16 steps
        float sc[8][4];
        #pragma unroll
        for (int ni = 0; ni < 8; ni++)
            #pragma unroll
            for (int j = 0; j < 4; j++) sc[ni][j] = 0.f;
        #pragma unroll
        for (int ks = 0; ks < 4; ks++) {
            uint32_t ko = (uint32_t)(ks * 32);
            uint32_t a[4];
            ldsm4(a, qaddr + ko);
            uint32_t bf[4][4];
            #pragma unroll
            for (int ng = 0; ng < 4; ng++) ldsm4(bf[ng], kaddr[ng] + ko);
            #pragma unroll
            for (int ni = 0; ni < 8; ni++) {
                int ng = ni >> 1, j = ni & 1;
                mma_f16(sc[ni], a, bf[ng][2 * j], bf[ng][2 * j + 1]);
            }
        }

        // softcap + causal + online softmax
        bool diag = (kb == qb);
        float mt0 = -INFINITY, mt1 = -INFINITY;
        #pragma unroll
        for (int ni = 0; ni < 8; ni++) {
            #pragma unroll
            for (int e = 0; e < 4; e++) {
                float y = sc[ni][e] * C1;
                float t = __expf(y + y);
                float v = 6.0f * (1.0f - __fdividef(2.0f, t + 1.0f));
                if (diag) {
                    int kcol = kb * 64 + ni * 8 + tg * 2 + (e & 1);
                    int qrow = qr0 + ((e >> 1) << 3);
                    if (kcol > qrow) v = -INFINITY;
                }
                sc[ni][e] = v;
                if (e < 2) mt0 = fmaxf(mt0, v); else mt1 = fmaxf(mt1, v);
            }
        }
        mt0 = fmaxf(mt0, __shfl_xor_sync(0xffffffffu, mt0, 1));
        mt0 = fmaxf(mt0, __shfl_xor_sync(0xffffffffu, mt0, 2));
        mt1 = fmaxf(mt1, __shfl_xor_sync(0xffffffffu, mt1, 1));
        mt1 = fmaxf(mt1, __shfl_xor_sync(0xffffffffu, mt1, 2));
        float mn0 = fmaxf(m0, mt0), mn1 = fmaxf(m1, mt1);
        float a0 = __expf(m0 - mn0), a1 = __expf(m1 - mn1);
        float s0 = 0.f, s1 = 0.f;
        __half* p0 = Ps + (wid * 16 + gid) * AST + tg * 2;
        __half* p1 = p0 + 8 * AST;
        #pragma unroll
        for (int ni = 0; ni < 8; ni++) {
            float e00 = __expf(sc[ni][0] - mn0);
            float e01 = __expf(sc[ni][1] - mn0);
            float e10 = __expf(sc[ni][2] - mn1);
            float e11 = __expf(sc[ni][3] - mn1);
            s0 += e00 + e01; s1 += e10 + e11;
            *(__half2*)(p0 + ni * 8) = __floats2half2_rn(e00, e01);
            *(__half2*)(p1 + ni * 8) = __floats2half2_rn(e10, e11);
        }
        s0 += __shfl_xor_sync(0xffffffffu, s0, 1);
        s0 += __shfl_xor_sync(0xffffffffu, s0, 2);
        s1 += __shfl_xor_sync(0xffffffffu, s1, 1);
        s1 += __shfl_xor_sync(0xffffffffu, s1, 2);
        l0 = l0 * a0 + s0; l1 = l1 * a1 + s1;
        m0 = mn0; m1 = mn1;
        #pragma unroll
        for (int ni = 0; ni < 8; ni++) {
            oa[ni][0] *= a0; oa[ni][1] *= a0;
            oa[ni][2] *= a1; oa[ni][3] *= a1;
        }
        __syncwarp();

        // O += P @ V  (A=P rows, B=V via trans ldmatrix), 64 keys -> 4 k16 steps
        #pragma unroll
        for (int ks = 0; ks < 4; ks++) {
            uint32_t a[4];
            ldsm4(a, paddr + (uint32_t)(ks * 32));
            uint32_t bf[4][4];
            uint32_t vo = (uint32_t)(ks * 16 * AST * 2);
            #pragma unroll
            for (int ng = 0; ng < 4; ng++) ldsm4t(bf[ng], vaddr[ng] + vo);
            #pragma unroll
            for (int ni = 0; ni < 8; ni++) {
                int ng = ni >> 1, j = ni & 1;
                mma_f16(oa[ni], a, bf[ng][2 * j], bf[ng][2 * j + 1]);
            }
        }
    }

    float inv0 = 1.0f / l0, inv1 = 1.0f / l1;
    __half* orow0 = o_out + (size_t)(b * S_ + qr0) * D_ + h * DH_ + tg * 2;
    __half* orow1 = orow0 + 8 * (size_t)D_;
    #pragma unroll
    for (int ni = 0; ni < 8; ni++) {
        *(__half2*)(orow0 + ni * 8) = __floats2half2_rn(oa[ni][0] * inv0, oa[ni][1] * inv0);
        *(__half2*)(orow1 + ni * 8) = __floats2half2_rn(oa[ni][2] * inv1, oa[ni][3] * inv1);
    }
}

// ---------------- launch ------------------------------------------------------
extern "C" void kernel_launch(void* const* d_in, const int* in_sizes, int n_in,
                              void* d_out, int out_size) {
    const float* x     = (const float*)d_in[0];
    const float* qkv_w = (const float*)d_in[2];
    const float* qkv_b = (const float*)d_in[3];
    const float* out_w = (const float*)d_in[4];
    const float* out_b = (const float*)d_in[5];
    const float* ln1_g = (const float*)d_in[6];
    const float* ln1_b = (const float*)d_in[7];
    const float* ln2_g = (const float*)d_in[8];
    const float* ln2_b = (const float*)d_in[9];
    const float* ff1_w = (const float*)d_in[10];
    const float* ff1_b = (const float*)d_in[11];
    const float* ff2_w = (const float*)d_in[12];
    const float* ff2_b = (const float*)d_in[13];
    float* out = (float*)d_out;

    __half *h, *qkv, *o, *ff, *w;
    float* x2;
    cudaGetSymbolAddress((void**)&h,   g_h_h);
    cudaGetSymbolAddress((void**)&qkv, g_qkv_h);
    cudaGetSymbolAddress((void**)&o,   g_o_h);
    cudaGetSymbolAddress((void**)&ff,  g_ff_h);
    cudaGetSymbolAddress((void**)&x2,  g_x2);
    cudaGetSymbolAddress((void**)&w,   g_wh);
    __half* w_qkv = w;
    __half* w_out = w + 3 * 1024 * 1024;
    __half* w_ff1 = w + 4 * 1024 * 1024;
    __half* w_ff2 = w + 6 * 1024 * 1024;

    cudaFuncSetAttribute(gemm_h_kernel, cudaFuncAttributeMaxDynamicSharedMemorySize, GH_SMEM);

    // 0. weights fp32 -> fp16
    w2h_kernel<<<(3*1024*1024/2 + 255)/256, 256>>>((const float2*)qkv_w, (__half2*)w_qkv, 3*1024*1024/2);
    w2h_kernel<<<(1024*1024/2   + 255)/256, 256>>>((const float2*)out_w, (__half2*)w_out, 1024*1024/2);
    w2h_kernel<<<(2*1024*1024/2 + 255)/256, 256>>>((const float2*)ff1_w, (__half2*)w_ff1, 2*1024*1024/2);
    w2h_kernel<<<(2*1024*1024/2 + 255)/256, 256>>>((const float2*)ff2_w, (__half2*)w_ff2, 2*1024*1024/2);

    // 1. h = LN1(x)  (fp16)
    ln_kernel<<<M_, 256>>>(x, ln1_g, ln1_b, h);
    // 2. qkv = h @ qkv_w^T + qkv_b  (fp16)
    gemm_h_kernel<<<dim3(3 * D_ / 128, M_ / 128), 256, GH_SMEM>>>(h, w_qkv, qkv_b, (const float*)0, (float*)0, qkv, 3 * D_, D_, 0);
    // 3. o = flash attention (fp16)
    attn_h_kernel<<<dim3(S_ / 64, H_, B_), 128>>>(qkv, o);
    // 4. x2 = x + o @ out_w^T + out_b  (fp32)
    gemm_h_kernel<<<dim3(D_ / 128, M_ / 128), 256, GH_SMEM>>>(o, w_out, out_b, x, x2, (__half*)0, D_, D_, 0);
    // 5. h = LN2(x2)  (fp16)
    ln_kernel<<<M_, 256>>>(x2, ln2_g, ln2_b, h);
    // 6. ff = gelu(h @ ff1_w^T + ff1_b)  (fp16)
    gemm_h_kernel<<<dim3(DF_ / 128, M_ / 128), 256, GH_SMEM>>>(h, w_ff1, ff1_b, (const float*)0, (float*)0, ff, DF_, D_, 1);
    // 7. out = x2 + ff @ ff2_w^T + ff2_b  (fp32)
    gemm_h_kernel<<<dim3(D_ / 128, M_ / 128), 256, GH_SMEM>>>(ff, w_ff2, ff2_b, x2, out, (__half*)0, D_, DF_, 0);
}

// round 6
// speedup vs baseline: 7.5768x; 1.0618x over previous
#include <cuda_runtime.h>
#include <cuda_fp16.h>
#include <math.h>
#include <stdint.h>

#define B_  4
#define S_  1024
#define D_  1024
#define H_  16
#define DH_ 64
#define DF_ 2048
#define M_  (B_*S_)

// ---------------- scratch (device globals) ----------------------------------
__device__ __half g_h_h[M_ * D_];
__device__ __half g_qkv_h[(size_t)M_ * 3 * D_];
__device__ __half g_o_h[M_ * D_];
__device__ __half g_ff_h[(size_t)M_ * DF_];
__device__ float  g_x2[M_ * D_];
__device__ __half g_wh[8 * 1024 * 1024];   // [0,3M) qkv, [3M,4M) out, [4M,6M) ff1, [6M,8M) ff2

// ---------------- helpers ----------------------------------------------------
__device__ __forceinline__ uint32_t smem_u32(const void* p) {
    uint32_t a;
    asm("{ .reg .u64 t; cvta.to.shared.u64 t, %1; cvt.u32.u64 %0, t; }" : "=r"(a) : "l"(p));
    return a;
}
__device__ __forceinline__ void cp16(uint32_t dst, const void* src) {
    asm volatile("cp.async.cg.shared.global [%0], [%1], 16;" :: "r"(dst), "l"(src) : "memory");
}
__device__ __forceinline__ void ldsm4(uint32_t* o, uint32_t addr) {
    asm volatile("ldmatrix.sync.aligned.m8n8.x4.shared.b16 {%0,%1,%2,%3}, [%4];"
                 : "=r"(o[0]), "=r"(o[1]), "=r"(o[2]), "=r"(o[3]) : "r"(addr));
}
__device__ __forceinline__ void ldsm4t(uint32_t* o, uint32_t addr) {
    asm volatile("ldmatrix.sync.aligned.m8n8.x4.trans.shared.b16 {%0,%1,%2,%3}, [%4];"
                 : "=r"(o[0]), "=r"(o[1]), "=r"(o[2]), "=r"(o[3]) : "r"(addr));
}
__device__ __forceinline__ void mma_f16(float* c, const uint32_t* a, uint32_t b0, uint32_t b1) {
    asm volatile(
        "mma.sync.aligned.m16n8k16.row.col.f32.f16.f16.f32 "
        "{%0,%1,%2,%3}, {%4,%5,%6,%7}, {%8,%9}, {%0,%1,%2,%3};"
        : "+f"(c[0]), "+f"(c[1]), "+f"(c[2]), "+f"(c[3])
        : "r"(a[0]), "r"(a[1]), "r"(a[2]), "r"(a[3]), "r"(b0), "r"(b1));
}

// ---------------- fused weight conversion fp32 -> fp16 -----------------------
// Segments (float2 units): qkv 1.5M, out 0.5M, ff1 1M, ff2 1M; dst layout matches.
#define W_N2 (4 * 1024 * 1024)
__global__ void w2h_all_kernel(const float2* __restrict__ qkv_w, const float2* __restrict__ out_w,
                               const float2* __restrict__ ff1_w, const float2* __restrict__ ff2_w,
                               __half2* __restrict__ d) {
    int i = blockIdx.x * blockDim.x + threadIdx.x;
    if (i >= W_N2) return;
    const int b0 = 1536 * 1024, b1 = 2048 * 1024, b2 = 3072 * 1024;
    float2 v;
    if (i < b0)      v = qkv_w[i];
    else if (i < b1) v = out_w[i - b0];
    else if (i < b2) v = ff1_w[i - b1];
    else             v = ff2_w[i - b2];
    d[i] = __float22half2_rn(v);
}

// ---------------- LayerNorm (fp32 in, fp16 out) ------------------------------
__global__ void ln_kernel(const float* __restrict__ x, const float* __restrict__ g,
                          const float* __restrict__ beta, __half* __restrict__ y) {
    __shared__ float red[8];
    int row = blockIdx.x;
    int tid = threadIdx.x;
    const float4* xr = (const float4*)(x + (size_t)row * D_);
    float4 v = xr[tid];
    float s = v.x + v.y + v.z + v.w;
    #pragma unroll
    for (int o = 16; o; o >>= 1) s += __shfl_xor_sync(0xffffffffu, s, o);
    if ((tid & 31) == 0) red[tid >> 5] = s;
    __syncthreads();
    float tot = 0.f;
    #pragma unroll
    for (int i = 0; i < 8; i++) tot += red[i];
    float mu = tot * (1.0f / (float)D_);
    __syncthreads();
    float dx = v.x - mu, dy = v.y - mu, dz = v.z - mu, dw = v.w - mu;
    float sq = dx*dx + dy*dy + dz*dz + dw*dw;
    #pragma unroll
    for (int o = 16; o; o >>= 1) sq += __shfl_xor_sync(0xffffffffu, sq, o);
    if ((tid & 31) == 0) red[tid >> 5] = sq;
    __syncthreads();
    float tot2 = 0.f;
    #pragma unroll
    for (int i = 0; i < 8; i++) tot2 += red[i];
    float inv = rsqrtf(tot2 * (1.0f / (float)D_) + 1e-5f);
    float4 gg = ((const float4*)g)[tid];
    float4 bb = ((const float4*)beta)[tid];
    __half2* yr = (__half2*)(y + (size_t)row * D_);
    yr[tid * 2]     = __floats2half2_rn(dx * inv * gg.x + bb.x, dy * inv * gg.y + bb.y);
    yr[tid * 2 + 1] = __floats2half2_rn(dz * inv * gg.z + bb.z, dw * inv * gg.w + bb.w);
}

// ---------------- fp16 mma GEMM, 4-stage cp.async pipeline -------------------
// CTA 128x128, BK=32 halves, 8 warps (4x2), warp tile 32x64.
#define GH_STRIDE 80
#define GH_HALF   (128 * GH_STRIDE)     // 10240 bytes (one operand, one stage)
#define GH_STAGE  (2 * GH_HALF)         // 20480
#define N_STAGES  4
#define GH_SMEM   (N_STAGES * GH_STAGE) // 81920

__global__ __launch_bounds__(256)
void gemm_h_kernel(const __half* __restrict__ A, const __half* __restrict__ Bw,
                   const float* __restrict__ bias, const float* __restrict__ res,
                   float* __restrict__ C, __half* __restrict__ Ch,
                   int N, int K, int act)
{
    extern __shared__ char smem[];
    uint32_t sb = smem_u32(smem);
    int tid = threadIdx.x;
    int lane = tid & 31, wid = tid >> 5;
    int wm = wid & 3, wn = wid >> 2;
    int bm = blockIdx.y << 7, bn = blockIdx.x << 7;

    int lrow = tid >> 1, lhalf = tid & 1;
    const __half* ag = A  + (size_t)(bm + lrow) * K + lhalf * 16;
    const __half* bg = Bw + (size_t)(bn + lrow) * K + lhalf * 16;
    uint32_t sda = sb + (uint32_t)lrow * GH_STRIDE + (uint32_t)lhalf * 32;
    uint32_t sdb = sda + GH_HALF;

    int sel = lane >> 3, rr = lane & 7;
    uint32_t aaddr[2], baddr[4];
    #pragma unroll
    for (int mi = 0; mi < 2; mi++) {
        int row = wm * 32 + mi * 16 + (sel & 1) * 8 + rr;
        aaddr[mi] = sb + (uint32_t)row * GH_STRIDE + (uint32_t)((sel >> 1) * 16);
    }
    #pragma unroll
    for (int ng = 0; ng < 4; ng++) {
        int row = wn * 64 + ng * 16 + (sel >> 1) * 8 + rr;
        baddr[ng] = sb + GH_HALF + (uint32_t)row * GH_STRIDE + (uint32_t)((sel & 1) * 16);
    }

    float acc[2][8][4];
    #pragma unroll
    for (int mi = 0; mi < 2; mi++)
        #pragma unroll
        for (int ni = 0; ni < 8; ni++)
            #pragma unroll
            for (int j = 0; j < 4; j++) acc[mi][ni][j] = 0.f;

    int nk = K >> 5;

    // prologue: stages 0..2
    #pragma unroll
    for (int st = 0; st < N_STAGES - 1; st++) {
        uint32_t so = (uint32_t)(st * GH_STAGE);
        const __half* ag2 = ag + (size_t)st * 32;
        const __half* bg2 = bg + (size_t)st * 32;
        #pragma unroll
        for (int c = 0; c < 2; c++) { cp16(sda + so + c * 16, ag2 + c * 8); cp16(sdb + so + c * 16, bg2 + c * 8); }
        asm volatile("cp.async.commit_group;" ::: "memory");
    }

    for (int kt = 0; kt < nk; kt++) {
        asm volatile("cp.async.wait_group %0;" :: "n"(N_STAGES - 2) : "memory");
        __syncthreads();

        // load stage kt+3 (ring slot (kt+3)%4 == (kt-1)%4, safe post-barrier)
        if (kt + N_STAGES - 1 < nk) {
            int st = kt + N_STAGES - 1;
            uint32_t so = (uint32_t)((st & (N_STAGES - 1)) * GH_STAGE);
            const __half* ag2 = ag + (size_t)st * 32;
            const __half* bg2 = bg + (size_t)st * 32;
            #pragma unroll
            for (int c = 0; c < 2; c++) { cp16(sda + so + c * 16, ag2 + c * 8); cp16(sdb + so + c * 16, bg2 + c * 8); }
        }
        asm volatile("cp.async.commit_group;" ::: "memory");

        uint32_t so = (uint32_t)((kt & (N_STAGES - 1)) * GH_STAGE);
        #pragma unroll
        for (int ks = 0; ks < 2; ks++) {
            uint32_t ko = so + (uint32_t)(ks * 32);
            uint32_t a[2][4];
            ldsm4(a[0], aaddr[0] + ko);
            ldsm4(a[1], aaddr[1] + ko);
            uint32_t b[4][4];
            #pragma unroll
            for (int ng = 0; ng < 4; ng++) ldsm4(b[ng], baddr[ng] + ko);
            #pragma unroll
            for (int mi = 0; mi < 2; mi++)
                #pragma unroll
                for (int ni = 0; ni < 8; ni++) {
                    int ng = ni >> 1, j = ni & 1;
                    mma_f16(acc[mi][ni], a[mi], b[ng][2 * j], b[ng][2 * j + 1]);
                }
        }
    }

    int gid = lane >> 2, tg = lane & 3;
    #pragma unroll
    for (int mi = 0; mi < 2; mi++) {
        #pragma unroll
        for (int half = 0; half < 2; half++) {
            int row = bm + wm * 32 + mi * 16 + half * 8 + gid;
            const float* rrow = res ? (res + (size_t)row * N) : (const float*)0;
            #pragma unroll
            for (int ni = 0; ni < 8; ni++) {
                int col = bn + wn * 64 + ni * 8 + tg * 2;
                float v0 = acc[mi][ni][half * 2 + 0] + __ldg(bias + col);
                float v1 = acc[mi][ni][half * 2 + 1] + __ldg(bias + col + 1);
                if (rrow) { v0 += rrow[col]; v1 += rrow[col + 1]; }
                if (act) {
                    v0 = 0.5f * v0 * (1.0f + erff(v0 * 0.70710678118654752f));
                    v1 = 0.5f * v1 * (1.0f + erff(v1 * 0.70710678118654752f));
                }
                if (Ch) {
                    *(__half2*)(Ch + (size_t)row * N + col) = __floats2half2_rn(v0, v1);
                } else {
                    *(float2*)(C + (size_t)row * N + col) = make_float2(v0, v1);
                }
            }
        }
    }
}

// ---------------- fp16 tensor-core flash attention ---------------------------
#define AST 72
__global__ __launch_bounds__(128)
void attn_h_kernel(const __half* __restrict__ qkv, __half* __restrict__ o_out) {
    __shared__ __half Qs[64 * AST];
    __shared__ __half Ks[64 * AST];
    __shared__ __half Vs[64 * AST];
    __shared__ __half Ps[64 * AST];

    int qb = blockIdx.x, h = blockIdx.y, b = blockIdx.z;
    int tid = threadIdx.x, lane = tid & 31, wid = tid >> 5;
    int gid = lane >> 2, tg = lane & 3;
    const size_t rstr = 3 * D_;
    const __half* base = qkv + (size_t)b * S_ * rstr + h * DH_;

    int lr = tid >> 1, lh = tid & 1;
    {
        const __half* qg = base + (size_t)(qb * 64 + lr) * rstr + lh * 32;
        __half* qs = Qs + lr * AST + lh * 32;
        #pragma unroll
        for (int i = 0; i < 32; i += 8) *(uint4*)(qs + i) = *(const uint4*)(qg + i);
    }

    uint32_t sQ = smem_u32(Qs), sK = smem_u32(Ks), sV = smem_u32(Vs), sP = smem_u32(Ps);
    int sel = lane >> 3, rr = lane & 7;
    uint32_t qaddr = sQ + (uint32_t)((wid * 16 + (sel & 1) * 8 + rr) * AST * 2) + (uint32_t)((sel >> 1) * 16);
    uint32_t paddr = sP + (uint32_t)((wid * 16 + (sel & 1) * 8 + rr) * AST * 2) + (uint32_t)((sel >> 1) * 16);
    uint32_t kaddr[4], vaddr[4];
    #pragma unroll
    for (int ng = 0; ng < 4; ng++) {
        kaddr[ng] = sK + (uint32_t)((ng * 16 + (sel >> 1) * 8 + rr) * AST * 2) + (uint32_t)((sel & 1) * 16);
        vaddr[ng] = sV + (uint32_t)(((sel & 1) * 8 + rr) * AST * 2) + (uint32_t)(ng * 32 + (sel >> 1) * 16);
    }

    float oa[8][4];
    #pragma unroll
    for (int ni = 0; ni < 8; ni++)
        #pragma unroll
        for (int j = 0; j < 4; j++) oa[ni][j] = 0.f;
    float m0 = -INFINITY, m1 = -INFINITY, l0 = 0.f, l1 = 0.f;
    int qr0 = qb * 64 + wid * 16 + gid;
    const float C1 = 0.125f / 6.0f;

    for (int kb = 0; kb <= qb; kb++) {
        __syncthreads();
        {
            const __half* kg = base + (size_t)(kb * 64 + lr) * rstr + D_ + lh * 32;
            __half* ks = Ks + lr * AST + lh * 32;
            #pragma unroll
            for (int i = 0; i < 32; i += 8) *(uint4*)(ks + i) = *(const uint4*)(kg + i);
            const __half* vg = base + (size_t)(kb * 64 + lr) * rstr + 2 * D_ + lh * 32;
            __half* vs = Vs + lr * AST + lh * 32;
            #pragma unroll
            for (int i = 0; i < 32; i += 8) *(uint4*)(vs + i) = *(const uint4*)(vg + i);
        }
        __syncthreads();

        float sc[8][4];
        #pragma unroll
        for (int ni = 0; ni < 8; ni++)
            #pragma unroll
            for (int j = 0; j < 4; j++) sc[ni][j] = 0.f;
        #pragma unroll
        for (int ks = 0; ks < 4; ks++) {
            uint32_t ko = (uint32_t)(ks * 32);
            uint32_t a[4];
            ldsm4(a, qaddr + ko);
            uint32_t bf[4][4];
            #pragma unroll
            for (int ng = 0; ng < 4; ng++) ldsm4(bf[ng], kaddr[ng] + ko);
            #pragma unroll
            for (int ni = 0; ni < 8; ni++) {
                int ng = ni >> 1, j = ni & 1;
                mma_f16(sc[ni], a, bf[ng][2 * j], bf[ng][2 * j + 1]);
            }
        }

        bool diag = (kb == qb);
        float mt0 = -INFINITY, mt1 = -INFINITY;
        #pragma unroll
        for (int ni = 0; ni < 8; ni++) {
            #pragma unroll
            for (int e = 0; e < 4; e++) {
                float y = sc[ni][e] * C1;
                float t = __expf(y + y);
                float v = 6.0f * (1.0f - __fdividef(2.0f, t + 1.0f));
                if (diag) {
                    int kcol = kb * 64 + ni * 8 + tg * 2 + (e & 1);
                    int qrow = qr0 + ((e >> 1) << 3);
                    if (kcol > qrow) v = -INFINITY;
                }
                sc[ni][e] = v;
                if (e < 2) mt0 = fmaxf(mt0, v); else mt1 = fmaxf(mt1, v);
            }
        }
        mt0 = fmaxf(mt0, __shfl_xor_sync(0xffffffffu, mt0, 1));
        mt0 = fmaxf(mt0, __shfl_xor_sync(0xffffffffu, mt0, 2));
        mt1 = fmaxf(mt1, __shfl_xor_sync(0xffffffffu, mt1, 1));
        mt1 = fmaxf(mt1, __shfl_xor_sync(0xffffffffu, mt1, 2));
        float mn0 = fmaxf(m0, mt0), mn1 = fmaxf(m1, mt1);
        float a0 = __expf(m0 - mn0), a1 = __expf(m1 - mn1);
        float s0 = 0.f, s1 = 0.f;
        __half* p0 = Ps + (wid * 16 + gid) * AST + tg * 2;
        __half* p1 = p0 + 8 * AST;
        #pragma unroll
        for (int ni = 0; ni < 8; ni++) {
            float e00 = __expf(sc[ni][0] - mn0);
            float e01 = __expf(sc[ni][1] - mn0);
            float e10 = __expf(sc[ni][2] - mn1);
            float e11 = __expf(sc[ni][3] - mn1);
            s0 += e00 + e01; s1 += e10 + e11;
            *(__half2*)(p0 + ni * 8) = __floats2half2_rn(e00, e01);
            *(__half2*)(p1 + ni * 8) = __floats2half2_rn(e10, e11);
        }
        s0 += __shfl_xor_sync(0xffffffffu, s0, 1);
        s0 += __shfl_xor_sync(0xffffffffu, s0, 2);
        s1 += __shfl_xor_sync(0xffffffffu, s1, 1);
        s1 += __shfl_xor_sync(0xffffffffu, s1, 2);
        l0 = l0 * a0 + s0; l1 = l1 * a1 + s1;
        m0 = mn0; m1 = mn1;
        #pragma unroll
        for (int ni = 0; ni < 8; ni++) {
            oa[ni][0] *= a0; oa[ni][1] *= a0;
            oa[ni][2] *= a1; oa[ni][3] *= a1;
        }
        __syncwarp();

        #pragma unroll
        for (int ks = 0; ks < 4; ks++) {
            uint32_t a[4];
            ldsm4(a, paddr + (uint32_t)(ks * 32));
            uint32_t bf[4][4];
            uint32_t vo = (uint32_t)(ks * 16 * AST * 2);
            #pragma unroll
            for (int ng = 0; ng < 4; ng++) ldsm4t(bf[ng], vaddr[ng] + vo);
            #pragma unroll
            for (int ni = 0; ni < 8; ni++) {
                int ng = ni >> 1, j = ni & 1;
                mma_f16(oa[ni], a, bf[ng][2 * j], bf[ng][2 * j + 1]);
            }
        }
    }

    float inv0 = 1.0f / l0, inv1 = 1.0f / l1;
    __half* orow0 = o_out + (size_t)(b * S_ + qr0) * D_ + h * DH_ + tg * 2;
    __half* orow1 = orow0 + 8 * (size_t)D_;
    #pragma unroll
    for (int ni = 0; ni < 8; ni++) {
        *(__half2*)(orow0 + ni * 8) = __floats2half2_rn(oa[ni][0] * inv0, oa[ni][1] * inv0);
        *(__half2*)(orow1 + ni * 8) = __floats2half2_rn(oa[ni][2] * inv1, oa[ni][3] * inv1);
    }
}

// ---------------- launch ------------------------------------------------------
extern "C" void kernel_launch(void* const* d_in, const int* in_sizes, int n_in,
                              void* d_out, int out_size) {
    const float* x     = (const float*)d_in[0];
    const float* qkv_w = (const float*)d_in[2];
    const float* qkv_b = (const float*)d_in[3];
    const float* out_w = (const float*)d_in[4];
    const float* out_b = (const float*)d_in[5];
    const float* ln1_g = (const float*)d_in[6];
    const float* ln1_b = (const float*)d_in[7];
    const float* ln2_g = (const float*)d_in[8];
    const float* ln2_b = (const float*)d_in[9];
    const float* ff1_w = (const float*)d_in[10];
    const float* ff1_b = (const float*)d_in[11];
    const float* ff2_w = (const float*)d_in[12];
    const float* ff2_b = (const float*)d_in[13];
    float* out = (float*)d_out;

    __half *h, *qkv, *o, *ff, *w;
    float* x2;
    cudaGetSymbolAddress((void**)&h,   g_h_h);
    cudaGetSymbolAddress((void**)&qkv, g_qkv_h);
    cudaGetSymbolAddress((void**)&o,   g_o_h);
    cudaGetSymbolAddress((void**)&ff,  g_ff_h);
    cudaGetSymbolAddress((void**)&x2,  g_x2);
    cudaGetSymbolAddress((void**)&w,   g_wh);
    __half* w_qkv = w;
    __half* w_out = w + 3 * 1024 * 1024;
    __half* w_ff1 = w + 4 * 1024 * 1024;
    __half* w_ff2 = w + 6 * 1024 * 1024;

    cudaFuncSetAttribute(gemm_h_kernel, cudaFuncAttributeMaxDynamicSharedMemorySize, GH_SMEM);

    // 0. all weights fp32 -> fp16 (single launch)
    w2h_all_kernel<<<W_N2 / 256, 256>>>((const float2*)qkv_w, (const float2*)out_w,
                                        (const float2*)ff1_w, (const float2*)ff2_w, (__half2*)w);

    // 1. h = LN1(x)
    ln_kernel<<<M_, 256>>>(x, ln1_g, ln1_b, h);
    // 2. qkv = h @ qkv_w^T + qkv_b
    gemm_h_kernel<<<dim3(3 * D_ / 128, M_ / 128), 256, GH_SMEM>>>(h, w_qkv, qkv_b, (const float*)0, (float*)0, qkv, 3 * D_, D_, 0);
    // 3. o = flash attention
    attn_h_kernel<<<dim3(S_ / 64, H_, B_), 128>>>(qkv, o);
    // 4. x2 = x + o @ out_w^T + out_b
    gemm_h_kernel<<<dim3(D_ / 128, M_ / 128), 256, GH_SMEM>>>(o, w_out, out_b, x, x2, (__half*)0, D_, D_, 0);
    // 5. h = LN2(x2)
    ln_kernel<<<M_, 256>>>(x2, ln2_g, ln2_b, h);
    // 6. ff = gelu(h @ ff1_w^T + ff1_b)
    gemm_h_kernel<<<dim3(DF_ / 128, M_ / 128), 256, GH_SMEM>>>(h, w_ff1, ff1_b, (const float*)0, (float*)0, ff, DF_, D_, 1);
    // 7. out = x2 + ff @ ff2_w^T + ff2_b
    gemm_h_kernel<<<dim3(D_ / 128, M_ / 128), 256, GH_SMEM>>>(ff, w_ff2, ff2_b, x2, out, (__half*)0, D_, DF_, 0);
}